// round 4
// baseline (speedup 1.0000x reference)
#include <cuda_runtime.h>
#include <cuda_bf16.h>
#include <cstdint>

#define N_NODES 100000
#define N_EDGES 1600000
#define D 128

// Scratch (allocation-free: __device__ globals)
__device__ int   g_cnt[N_NODES];
__device__ int   g_cursor[N_NODES];
__device__ int   g_rowstart[N_NODES + 1];
__device__ int   g_csrsrc[N_EDGES];
__device__ float g_agg[(size_t)N_NODES * D];
__device__ float g_h1[(size_t)N_NODES * D];

// ---------------------------------------------------------------- helpers
__device__ __forceinline__ uint32_t f2tf32(float x) {
    uint32_t r;
    asm("cvt.rna.tf32.f32 %0, %1;" : "=r"(r) : "f"(x));
    return r;
}
__device__ __forceinline__ void mma_tf32(float* d, const uint32_t* a, const uint32_t* b) {
    asm volatile(
        "mma.sync.aligned.m16n8k8.row.col.f32.tf32.tf32.f32 "
        "{%0,%1,%2,%3}, {%4,%5,%6,%7}, {%8,%9}, {%0,%1,%2,%3};"
        : "+f"(d[0]), "+f"(d[1]), "+f"(d[2]), "+f"(d[3])
        : "r"(a[0]), "r"(a[1]), "r"(a[2]), "r"(a[3]), "r"(b[0]), "r"(b[1]));
}

// ---------------------------------------------------------------- CSR build
__global__ void hist_kernel(const int* __restrict__ dst, int* __restrict__ cnt, int E) {
    int i = blockIdx.x * blockDim.x + threadIdx.x;
    if (i < E) atomicAdd(&cnt[dst[i]], 1);
}

__global__ void scan_kernel(const int* __restrict__ cnt, int* __restrict__ rowstart,
                            int* __restrict__ cursor, int n) {
    __shared__ int sums[1024];
    int tid = threadIdx.x;
    int per = (n + 1023) / 1024;
    int beg = tid * per;
    int end = min(beg + per, n);
    int s = 0;
    for (int i = beg; i < end; i++) s += cnt[i];
    sums[tid] = s;
    __syncthreads();
#pragma unroll
    for (int off = 1; off < 1024; off <<= 1) {
        int t = (tid >= off) ? sums[tid - off] : 0;
        __syncthreads();
        sums[tid] += t;
        __syncthreads();
    }
    int run = sums[tid] - s;
    for (int i = beg; i < end; i++) {
        rowstart[i] = run;
        cursor[i] = run;
        run += cnt[i];
    }
    if (tid == 1023) rowstart[n] = sums[1023];
}

__global__ void fill_kernel(const int* __restrict__ src, const int* __restrict__ dst,
                            int* __restrict__ cursor, int* __restrict__ csrsrc, int E) {
    int i = blockIdx.x * blockDim.x + threadIdx.x;
    if (i < E) {
        int pos = atomicAdd(&cursor[dst[i]], 1);
        csrsrc[pos] = src[i];
    }
}

// ---------------------------------------------------------------- aggregation
__global__ void gather_kernel(const float* __restrict__ H, const int* __restrict__ rowstart,
                              const int* __restrict__ csrsrc, float* __restrict__ agg, int N) {
    int w = (blockIdx.x * blockDim.x + threadIdx.x) >> 5;
    int lane = threadIdx.x & 31;
    if (w >= N) return;
    int beg = __ldg(rowstart + w);
    int end = __ldg(rowstart + w + 1);
    float4 a0 = make_float4(0.f, 0.f, 0.f, 0.f);
    float4 a1 = make_float4(0.f, 0.f, 0.f, 0.f);
    int i = beg;
    for (; i + 1 < end; i += 2) {
        int s0 = __ldg(csrsrc + i);
        int s1 = __ldg(csrsrc + i + 1);
        float4 v0 = __ldg((const float4*)(H + (size_t)s0 * D) + lane);
        float4 v1 = __ldg((const float4*)(H + (size_t)s1 * D) + lane);
        a0.x += v0.x; a0.y += v0.y; a0.z += v0.z; a0.w += v0.w;
        a1.x += v1.x; a1.y += v1.y; a1.z += v1.z; a1.w += v1.w;
    }
    if (i < end) {
        int s0 = __ldg(csrsrc + i);
        float4 v0 = __ldg((const float4*)(H + (size_t)s0 * D) + lane);
        a0.x += v0.x; a0.y += v0.y; a0.z += v0.z; a0.w += v0.w;
    }
    float inv = 1.0f / (float)max(end - beg, 1);
    float4 r = make_float4((a0.x + a1.x) * inv, (a0.y + a1.y) * inv,
                           (a0.z + a1.z) * inv, (a0.w + a1.w) * inv);
    *((float4*)(agg + (size_t)w * D) + lane) = r;
}

// ---------------------------------------------------------------- tf32 mma GEMM
// out[M,128] = relu?( X @ Wself + AGG @ Wneigh + bias ); mode1: fused classifier
// CTA: 128x128 tile, 256 threads = 8 warps in 4(m) x 2(n) grid.
// Warp computes 32x64 via m16n8k8 fragments: 2 m-tiles x 8 n-tiles.
// SMEM staging packs operands in fragment order:
//   A frag elem (r,c): mtile=r>>4, kstep=c>>3, lane=((r&7)*4)|(c&3),
//                      slot=((r>>3)&1)|(((c>>2)&1)<<1)
//   B frag elem (k,n): ntile=n>>3, kstep=k>>3, lane=((n&7)*4)|(k&3), slot=(k>>2)&1
__global__ void __launch_bounds__(256)
gemm_sage_mma(const float* __restrict__ X, const float* __restrict__ AGG,
              const float* __restrict__ Wself, const float* __restrict__ Wneigh,
              const float* __restrict__ bias, float* __restrict__ out, int M, int mode,
              const float* __restrict__ Wc, const float* __restrict__ bc,
              float* __restrict__ out2) {
    __shared__ __align__(16) uint32_t As[4096];  // 128m x 32k, fragment-packed
    __shared__ __align__(16) uint32_t Bs[4096];  // 32k x 128n, fragment-packed
    __shared__ float s_cls[2][128][2];

    int tid = threadIdx.x;
    int wid = tid >> 5;
    int lane = tid & 31;
    int wm = wid >> 1;   // 0..3
    int wn = wid & 1;    // 0..1
    int row0 = blockIdx.x * 128;

    float acc[2][8][4];
#pragma unroll
    for (int mt = 0; mt < 2; mt++)
#pragma unroll
        for (int nt = 0; nt < 8; nt++)
#pragma unroll
            for (int e = 0; e < 4; e++) acc[mt][nt][e] = 0.f;

    // staging maps (constant per thread)
    int a_r = tid >> 3;            // +it*32
    int a_c0 = (tid & 7) * 4;      // chunk-local col
    int b_k = tid >> 5;            // +it*8, chunk-local k
    int b_n0 = (tid & 31) * 4;

#pragma unroll 1
    for (int phase = 0; phase < 2; ++phase) {
        const float* A = phase ? AGG : X;
        const float* W = phase ? Wneigh : Wself;
#pragma unroll 1
        for (int kc = 0; kc < 4; ++kc) {
            int k0 = kc * 32;
            __syncthreads();
            // stage A: 128 x 32 chunk
#pragma unroll
            for (int it = 0; it < 4; it++) {
                int r = a_r + it * 32;
                int gr = min(row0 + r, M - 1);
                float4 v = __ldg((const float4*)(A + (size_t)gr * D + k0 + a_c0));
                float f[4] = {v.x, v.y, v.z, v.w};
                int mtile = r >> 4;
                int kstep = a_c0 >> 3;
                int slot = ((r >> 3) & 1) | (((a_c0 >> 2) & 1) << 1);
                int lbase = (r & 7) * 4;
                uint32_t base = (uint32_t)(((mtile * 4 + kstep) * 32) * 4 + slot);
#pragma unroll
                for (int e = 0; e < 4; e++)
                    As[base + (lbase + e) * 4] = f2tf32(f[e]);
            }
            // stage B: 32 x 128 chunk (W rows k0..k0+31)
#pragma unroll
            for (int it = 0; it < 4; it++) {
                int k = b_k + it * 8;
                float4 w = __ldg((const float4*)(W + (size_t)(k0 + k) * D + b_n0));
                float f[4] = {w.x, w.y, w.z, w.w};
                int kstep = k >> 3;
                int slot = (k >> 2) & 1;
                int kl = k & 3;
#pragma unroll
                for (int e = 0; e < 4; e++) {
                    int n = b_n0 + e;
                    int ntile = n >> 3;
                    uint32_t addr = (uint32_t)((((ntile * 4 + kstep) * 32) +
                                               ((n & 7) * 4 + kl)) * 2 + slot);
                    Bs[addr] = f2tf32(f[e]);
                }
            }
            __syncthreads();
            // compute: 4 k-steps of 8
#pragma unroll
            for (int ks = 0; ks < 4; ks++) {
                uint4 af[2];
#pragma unroll
                for (int mt = 0; mt < 2; mt++)
                    af[mt] = ((const uint4*)As)[((wm * 2 + mt) * 4 + ks) * 32 + lane];
#pragma unroll
                for (int nt = 0; nt < 8; nt++) {
                    uint2 bf = ((const uint2*)Bs)[((wn * 8 + nt) * 4 + ks) * 32 + lane];
                    uint32_t b2[2] = {bf.x, bf.y};
#pragma unroll
                    for (int mt = 0; mt < 2; mt++)
                        mma_tf32(acc[mt][nt], (const uint32_t*)&af[mt], b2);
                }
            }
        }
    }

    // ---------------- epilogue ----------------
    // D frag: d0 (r=lane>>2, c=(lane&3)*2), d1 (c+1), d2 (r+8), d3 (r+8,c+1)
    if (mode == 0) {
#pragma unroll
        for (int mt = 0; mt < 2; mt++) {
            int r = row0 + wm * 32 + mt * 16 + (lane >> 2);
#pragma unroll
            for (int nt = 0; nt < 8; nt++) {
                int c = wn * 64 + nt * 8 + (lane & 3) * 2;
                float b0 = __ldg(bias + c), b1 = __ldg(bias + c + 1);
                if (r < M) {
                    float2 o = make_float2(fmaxf(acc[mt][nt][0] + b0, 0.f),
                                           fmaxf(acc[mt][nt][1] + b1, 0.f));
                    *(float2*)(out + (size_t)r * D + c) = o;
                }
                if (r + 8 < M) {
                    float2 o = make_float2(fmaxf(acc[mt][nt][2] + b0, 0.f),
                                           fmaxf(acc[mt][nt][3] + b1, 0.f));
                    *(float2*)(out + (size_t)(r + 8) * D + c) = o;
                }
            }
        }
    } else {
#pragma unroll
        for (int mt = 0; mt < 2; mt++) {
            float p00 = 0.f, p01 = 0.f, p10 = 0.f, p11 = 0.f;  // [rowpair][class]
#pragma unroll
            for (int nt = 0; nt < 8; nt++) {
                int c = wn * 64 + nt * 8 + (lane & 3) * 2;
                float b0 = __ldg(bias + c), b1 = __ldg(bias + c + 1);
                float2 w0 = __ldg((const float2*)(Wc + (size_t)c * 2));
                float2 w1 = __ldg((const float2*)(Wc + (size_t)(c + 1) * 2));
                float h0 = acc[mt][nt][0] + b0, h1 = acc[mt][nt][1] + b1;
                float h2 = acc[mt][nt][2] + b0, h3 = acc[mt][nt][3] + b1;
                p00 += h0 * w0.x + h1 * w1.x;
                p01 += h0 * w0.y + h1 * w1.y;
                p10 += h2 * w0.x + h3 * w1.x;
                p11 += h2 * w0.y + h3 * w1.y;
            }
#pragma unroll
            for (int off = 1; off <= 2; off <<= 1) {
                p00 += __shfl_xor_sync(0xFFFFFFFFu, p00, off);
                p01 += __shfl_xor_sync(0xFFFFFFFFu, p01, off);
                p10 += __shfl_xor_sync(0xFFFFFFFFu, p10, off);
                p11 += __shfl_xor_sync(0xFFFFFFFFu, p11, off);
            }
            if ((lane & 3) == 0) {
                int lr = wm * 32 + mt * 16 + (lane >> 2);
                s_cls[wn][lr][0] = p00;
                s_cls[wn][lr][1] = p01;
                s_cls[wn][lr + 8][0] = p10;
                s_cls[wn][lr + 8][1] = p11;
            }
        }
        __syncthreads();
        {
            int row = tid >> 1;
            int j = tid & 1;
            if (row0 + row < M) {
                float v = s_cls[0][row][j] + s_cls[1][row][j] + __ldg(bc + j);
                out2[(size_t)(row0 + row) * 2 + j] = v;
            }
        }
    }
}

// ---------------------------------------------------------------- launch
extern "C" void kernel_launch(void* const* d_in, const int* in_sizes, int n_in,
                              void* d_out, int out_size) {
    const float* features = (const float*)d_in[0];
    const int*   src      = (const int*)d_in[1];
    const int*   dst      = (const int*)d_in[2];
    const float* W1s      = (const float*)d_in[3];
    const float* W1n      = (const float*)d_in[4];
    const float* b1       = (const float*)d_in[5];
    const float* W2s      = (const float*)d_in[6];
    const float* W2n      = (const float*)d_in[7];
    const float* b2       = (const float*)d_in[8];
    const float* Wc       = (const float*)d_in[9];
    const float* bc       = (const float*)d_in[10];

    int N = in_sizes[0] / D;
    int E = in_sizes[1];

    int *cnt, *cursor, *rowstart, *csrsrc;
    float *agg, *h1;
    cudaGetSymbolAddress((void**)&cnt, g_cnt);
    cudaGetSymbolAddress((void**)&cursor, g_cursor);
    cudaGetSymbolAddress((void**)&rowstart, g_rowstart);
    cudaGetSymbolAddress((void**)&csrsrc, g_csrsrc);
    cudaGetSymbolAddress((void**)&agg, g_agg);
    cudaGetSymbolAddress((void**)&h1, g_h1);

    int mblocks = (N + 127) / 128;
    int gblocks = (N + 7) / 8;

    cudaMemsetAsync(cnt, 0, (size_t)N * sizeof(int));
    hist_kernel<<<(E + 255) / 256, 256>>>(dst, cnt, E);
    scan_kernel<<<1, 1024>>>(cnt, rowstart, cursor, N);
    fill_kernel<<<(E + 255) / 256, 256>>>(src, dst, cursor, csrsrc, E);

    gather_kernel<<<gblocks, 256>>>(features, rowstart, csrsrc, agg, N);
    gemm_sage_mma<<<mblocks, 256>>>(features, agg, W1s, W1n, b1, h1, N, 0,
                                    nullptr, nullptr, nullptr);

    gather_kernel<<<gblocks, 256>>>(h1, rowstart, csrsrc, agg, N);
    gemm_sage_mma<<<mblocks, 256>>>(h1, agg, W2s, W2n, b2, nullptr, N, 1,
                                    Wc, bc, (float*)d_out);
}

// round 5
// speedup vs baseline: 1.5678x; 1.5678x over previous
#include <cuda_runtime.h>
#include <cuda_bf16.h>
#include <cstdint>

#define N_NODES 100000
#define N_EDGES 1600000
#define D 128

// Scratch (allocation-free: __device__ globals)
__device__ int   g_cnt[N_NODES];
__device__ int   g_cursor[N_NODES];
__device__ int   g_rowstart[N_NODES + 1];
__device__ int   g_csrsrc[N_EDGES];
__device__ float g_agg[(size_t)N_NODES * D];
__device__ float g_h1[(size_t)N_NODES * D];

// ---------------------------------------------------------------- helpers
__device__ __forceinline__ uint32_t f2tf32(float x) {
    uint32_t r;
    asm("cvt.rna.tf32.f32 %0, %1;" : "=r"(r) : "f"(x));
    return r;
}
__device__ __forceinline__ void mma_tf32(float* d, const uint32_t* a, const uint32_t* b) {
    asm volatile(
        "mma.sync.aligned.m16n8k8.row.col.f32.tf32.tf32.f32 "
        "{%0,%1,%2,%3}, {%4,%5,%6,%7}, {%8,%9}, {%0,%1,%2,%3};"
        : "+f"(d[0]), "+f"(d[1]), "+f"(d[2]), "+f"(d[3])
        : "r"(a[0]), "r"(a[1]), "r"(a[2]), "r"(a[3]), "r"(b[0]), "r"(b[1]));
}

// ---------------------------------------------------------------- CSR build
__global__ void zero_cnt_kernel(int* __restrict__ cnt, int n) {
    int i = blockIdx.x * blockDim.x + threadIdx.x;
    if (i < n) cnt[i] = 0;
}

__global__ void hist_kernel(const int* __restrict__ dst, int* __restrict__ cnt, int E) {
    int i = blockIdx.x * blockDim.x + threadIdx.x;
    if (i < E) atomicAdd(&cnt[dst[i]], 1);
}

__global__ void scan_kernel(const int* __restrict__ cnt, int* __restrict__ rowstart,
                            int* __restrict__ cursor, int n) {
    __shared__ int sums[1024];
    int tid = threadIdx.x;
    int per = (n + 1023) / 1024;
    int beg = tid * per;
    int end = min(beg + per, n);
    int s = 0;
    for (int i = beg; i < end; i++) s += cnt[i];
    sums[tid] = s;
    __syncthreads();
#pragma unroll
    for (int off = 1; off < 1024; off <<= 1) {
        int t = (tid >= off) ? sums[tid - off] : 0;
        __syncthreads();
        sums[tid] += t;
        __syncthreads();
    }
    int run = sums[tid] - s;
    for (int i = beg; i < end; i++) {
        rowstart[i] = run;
        cursor[i] = run;
        run += cnt[i];
    }
    if (tid == 1023) rowstart[n] = sums[1023];
}

__global__ void fill_kernel(const int* __restrict__ src, const int* __restrict__ dst,
                            int* __restrict__ cursor, int* __restrict__ csrsrc, int E) {
    int i = blockIdx.x * blockDim.x + threadIdx.x;
    if (i < E) {
        int pos = atomicAdd(&cursor[dst[i]], 1);
        csrsrc[pos] = src[i];
    }
}

// ---------------------------------------------------------------- aggregation
__global__ void gather_kernel(const float* __restrict__ H, const int* __restrict__ rowstart,
                              const int* __restrict__ csrsrc, float* __restrict__ agg, int N) {
    int w = (blockIdx.x * blockDim.x + threadIdx.x) >> 5;
    int lane = threadIdx.x & 31;
    if (w >= N) return;
    int beg = __ldg(rowstart + w);
    int end = __ldg(rowstart + w + 1);
    float4 a0 = make_float4(0.f, 0.f, 0.f, 0.f);
    float4 a1 = make_float4(0.f, 0.f, 0.f, 0.f);
    int i = beg;
    for (; i + 1 < end; i += 2) {
        int s0 = __ldg(csrsrc + i);
        int s1 = __ldg(csrsrc + i + 1);
        float4 v0 = __ldg((const float4*)(H + (size_t)s0 * D) + lane);
        float4 v1 = __ldg((const float4*)(H + (size_t)s1 * D) + lane);
        a0.x += v0.x; a0.y += v0.y; a0.z += v0.z; a0.w += v0.w;
        a1.x += v1.x; a1.y += v1.y; a1.z += v1.z; a1.w += v1.w;
    }
    if (i < end) {
        int s0 = __ldg(csrsrc + i);
        float4 v0 = __ldg((const float4*)(H + (size_t)s0 * D) + lane);
        a0.x += v0.x; a0.y += v0.y; a0.z += v0.z; a0.w += v0.w;
    }
    float inv = 1.0f / (float)max(end - beg, 1);
    float4 r = make_float4((a0.x + a1.x) * inv, (a0.y + a1.y) * inv,
                           (a0.z + a1.z) * inv, (a0.w + a1.w) * inv);
    *((float4*)(agg + (size_t)w * D) + lane) = r;
}

// ---------------------------------------------------------------- tf32 mma GEMM
// out[M,128] = relu?( X @ Wself + AGG @ Wneigh + bias ); mode1: fused classifier
// CTA 128x128, 256 threads = 8 warps in 4(m)x2(n); warp tile 32x64 (2 x 8 m16n8k8).
// SMEM: XOR-swizzled row-major (conflict-free both producer STS.128 and
// consumer scalar LDS, see analysis):
//   A[r][c]: float idx = r*32 + ((c>>2)^(r&7))*4 + (c&3)
//   B[k][n]: float idx = k*128 + ((n>>2)^((k&3)<<1))*4 + (n&3)
__global__ void __launch_bounds__(256, 2)
gemm_sage_mma(const float* __restrict__ X, const float* __restrict__ AGG,
              const float* __restrict__ Wself, const float* __restrict__ Wneigh,
              const float* __restrict__ bias, float* __restrict__ out, int M, int mode,
              const float* __restrict__ Wc, const float* __restrict__ bc,
              float* __restrict__ out2) {
    __shared__ __align__(16) uint32_t As[128 * 32];  // 16 KB
    __shared__ __align__(16) uint32_t Bs[32 * 128];  // 16 KB
    __shared__ float s_cls[2][128][2];

    int tid = threadIdx.x;
    int wid = tid >> 5;
    int lane = tid & 31;
    int wm = wid >> 1;   // 0..3
    int wn = wid & 1;    // 0..1
    int row0 = blockIdx.x * 128;

    float acc[2][8][4];
#pragma unroll
    for (int mt = 0; mt < 2; mt++)
#pragma unroll
        for (int nt = 0; nt < 8; nt++)
#pragma unroll
            for (int e = 0; e < 4; e++) acc[mt][nt][e] = 0.f;

    // producer maps
    int a_r = tid >> 3;            // +it*32 ; warp covers 4 rows x 32 cols
    int a_v = tid & 7;             // float4 index within row (c0 = a_v*4)
    int b_lane4 = lane;            // B: n-vec = lane, k = wid + it*8
    int b_swz = (wid & 3) << 1;    // (k&3)<<1, const per warp

    // consumer maps (precomputed pieces)
    int r0l = wm * 32 + (lane >> 2);         // + mt*16
    int c_lo = lane & 3;
    int n_q = lane >> 2;                      // n offset within ntile

#pragma unroll 1
    for (int phase = 0; phase < 2; ++phase) {
        const float* A = phase ? AGG : X;
        const float* W = phase ? Wneigh : Wself;
#pragma unroll 1
        for (int kc = 0; kc < 4; ++kc) {
            int k0 = kc * 32;
            __syncthreads();
            // stage A: 128 x 32 chunk (coalesced LDG, conflict-free STS.128)
#pragma unroll
            for (int it = 0; it < 4; it++) {
                int r = a_r + it * 32;
                int gr = min(row0 + r, M - 1);
                float4 v = __ldg((const float4*)(A + (size_t)gr * D + k0 + a_v * 4));
                uint4 t;
                t.x = f2tf32(v.x); t.y = f2tf32(v.y);
                t.z = f2tf32(v.z); t.w = f2tf32(v.w);
                ((uint4*)As)[r * 8 + (a_v ^ (r & 7))] = t;
            }
            // stage B: 32 x 128 chunk (one k-row per warp per it)
#pragma unroll
            for (int it = 0; it < 4; it++) {
                int k = wid + it * 8;
                float4 w = __ldg((const float4*)(W + (size_t)(k0 + k) * D + b_lane4 * 4));
                uint4 t;
                t.x = f2tf32(w.x); t.y = f2tf32(w.y);
                t.z = f2tf32(w.z); t.w = f2tf32(w.w);
                ((uint4*)Bs)[k * 32 + (b_lane4 ^ b_swz)] = t;
            }
            __syncthreads();
            // compute: 4 k-steps of 8
#pragma unroll
            for (int ks = 0; ks < 4; ks++) {
                uint32_t af[2][4];
#pragma unroll
                for (int mt = 0; mt < 2; mt++) {
                    int r = r0l + mt * 16;
                    int base = r * 32 + c_lo;
                    int v0 = ((2 * ks) ^ (r & 7)) * 4;
                    int v1 = ((2 * ks + 1) ^ (r & 7)) * 4;
                    af[mt][0] = As[base + v0];
                    af[mt][1] = As[base + v0 + 256];
                    af[mt][2] = As[base + v1];
                    af[mt][3] = As[base + v1 + 256];
                }
                int kf = ks * 8 + c_lo;
                int kbase = kf * 128 + (n_q & 3);
                int kswz = (kf & 3) << 1;
#pragma unroll
                for (int nt = 0; nt < 8; nt++) {
                    int n = wn * 64 + nt * 8 + n_q;
                    int vv = ((n >> 2) ^ kswz) * 4;
                    uint32_t b2[2];
                    b2[0] = Bs[kbase + vv];
                    b2[1] = Bs[kbase + vv + 512];
#pragma unroll
                    for (int mt = 0; mt < 2; mt++)
                        mma_tf32(acc[mt][nt], af[mt], b2);
                }
            }
        }
    }

    // ---------------- epilogue ----------------
    if (mode == 0) {
#pragma unroll
        for (int mt = 0; mt < 2; mt++) {
            int r = row0 + wm * 32 + mt * 16 + (lane >> 2);
#pragma unroll
            for (int nt = 0; nt < 8; nt++) {
                int c = wn * 64 + nt * 8 + (lane & 3) * 2;
                float b0 = __ldg(bias + c), b1 = __ldg(bias + c + 1);
                if (r < M) {
                    float2 o = make_float2(fmaxf(acc[mt][nt][0] + b0, 0.f),
                                           fmaxf(acc[mt][nt][1] + b1, 0.f));
                    *(float2*)(out + (size_t)r * D + c) = o;
                }
                if (r + 8 < M) {
                    float2 o = make_float2(fmaxf(acc[mt][nt][2] + b0, 0.f),
                                           fmaxf(acc[mt][nt][3] + b1, 0.f));
                    *(float2*)(out + (size_t)(r + 8) * D + c) = o;
                }
            }
        }
    } else {
#pragma unroll
        for (int mt = 0; mt < 2; mt++) {
            float p00 = 0.f, p01 = 0.f, p10 = 0.f, p11 = 0.f;
#pragma unroll
            for (int nt = 0; nt < 8; nt++) {
                int c = wn * 64 + nt * 8 + (lane & 3) * 2;
                float b0 = __ldg(bias + c), b1 = __ldg(bias + c + 1);
                float2 w0 = __ldg((const float2*)(Wc + (size_t)c * 2));
                float2 w1 = __ldg((const float2*)(Wc + (size_t)(c + 1) * 2));
                float h0 = acc[mt][nt][0] + b0, h1 = acc[mt][nt][1] + b1;
                float h2 = acc[mt][nt][2] + b0, h3 = acc[mt][nt][3] + b1;
                p00 += h0 * w0.x + h1 * w1.x;
                p01 += h0 * w0.y + h1 * w1.y;
                p10 += h2 * w0.x + h3 * w1.x;
                p11 += h2 * w0.y + h3 * w1.y;
            }
#pragma unroll
            for (int off = 1; off <= 2; off <<= 1) {
                p00 += __shfl_xor_sync(0xFFFFFFFFu, p00, off);
                p01 += __shfl_xor_sync(0xFFFFFFFFu, p01, off);
                p10 += __shfl_xor_sync(0xFFFFFFFFu, p10, off);
                p11 += __shfl_xor_sync(0xFFFFFFFFu, p11, off);
            }
            if ((lane & 3) == 0) {
                int lr = wm * 32 + mt * 16 + (lane >> 2);
                s_cls[wn][lr][0] = p00;
                s_cls[wn][lr][1] = p01;
                s_cls[wn][lr + 8][0] = p10;
                s_cls[wn][lr + 8][1] = p11;
            }
        }
        __syncthreads();
        {
            int row = tid >> 1;
            int j = tid & 1;
            if (row0 + row < M) {
                float v = s_cls[0][row][j] + s_cls[1][row][j] + __ldg(bc + j);
                out2[(size_t)(row0 + row) * 2 + j] = v;
            }
        }
    }
}

// ---------------------------------------------------------------- launch
extern "C" void kernel_launch(void* const* d_in, const int* in_sizes, int n_in,
                              void* d_out, int out_size) {
    const float* features = (const float*)d_in[0];
    const int*   src      = (const int*)d_in[1];
    const int*   dst      = (const int*)d_in[2];
    const float* W1s      = (const float*)d_in[3];
    const float* W1n      = (const float*)d_in[4];
    const float* b1       = (const float*)d_in[5];
    const float* W2s      = (const float*)d_in[6];
    const float* W2n      = (const float*)d_in[7];
    const float* b2       = (const float*)d_in[8];
    const float* Wc       = (const float*)d_in[9];
    const float* bc       = (const float*)d_in[10];

    int N = in_sizes[0] / D;
    int E = in_sizes[1];

    int *cnt, *cursor, *rowstart, *csrsrc;
    float *agg, *h1;
    cudaGetSymbolAddress((void**)&cnt, g_cnt);
    cudaGetSymbolAddress((void**)&cursor, g_cursor);
    cudaGetSymbolAddress((void**)&rowstart, g_rowstart);
    cudaGetSymbolAddress((void**)&csrsrc, g_csrsrc);
    cudaGetSymbolAddress((void**)&agg, g_agg);
    cudaGetSymbolAddress((void**)&h1, g_h1);

    int mblocks = (N + 127) / 128;
    int gblocks = (N + 7) / 8;

    // launches (ncu -s 5 -c 1 -> profiles launch index 5 = gemm1)
    zero_cnt_kernel<<<(N + 255) / 256, 256>>>(cnt, N);            // 0
    hist_kernel<<<(E + 255) / 256, 256>>>(dst, cnt, E);           // 1
    scan_kernel<<<1, 1024>>>(cnt, rowstart, cursor, N);           // 2
    fill_kernel<<<(E + 255) / 256, 256>>>(src, dst, cursor, csrsrc, E);  // 3

    gather_kernel<<<gblocks, 256>>>(features, rowstart, csrsrc, agg, N); // 4
    gemm_sage_mma<<<mblocks, 256>>>(features, agg, W1s, W1n, b1, h1, N, 0,
                                    nullptr, nullptr, nullptr);          // 5
    gather_kernel<<<gblocks, 256>>>(h1, rowstart, csrsrc, agg, N);       // 6
    gemm_sage_mma<<<mblocks, 256>>>(h1, agg, W2s, W2n, b2, nullptr, N, 1,
                                    Wc, bc, (float*)d_out);              // 7
}

// round 7
// speedup vs baseline: 1.8337x; 1.1696x over previous
#include <cuda_runtime.h>
#include <cuda_fp16.h>
#include <cstdint>

#define N_NODES 100000
#define N_EDGES 1600000
#define D 128

// Scratch (allocation-free: __device__ globals)
__device__ int    g_cnt[N_NODES];
__device__ int    g_cursor[N_NODES];
__device__ int    g_rowstart[N_NODES + 1];
__device__ int    g_csrsrc[N_EDGES];
__device__ __half g_feat16[(size_t)N_NODES * D];
__device__ __half g_agg16[(size_t)N_NODES * D];
__device__ __half g_h116[(size_t)N_NODES * D];
__device__ __half g_w16[4][D * D];   // [0]=W1s^T,[1]=W1n^T,[2]=W2s^T,[3]=W2n^T  (n-major)

// ---------------------------------------------------------------- helpers
__device__ __forceinline__ void mma_f16(float* d, const uint32_t* a, const uint32_t* b) {
    asm volatile(
        "mma.sync.aligned.m16n8k16.row.col.f32.f16.f16.f32 "
        "{%0,%1,%2,%3}, {%4,%5,%6,%7}, {%8,%9}, {%0,%1,%2,%3};"
        : "+f"(d[0]), "+f"(d[1]), "+f"(d[2]), "+f"(d[3])
        : "r"(a[0]), "r"(a[1]), "r"(a[2]), "r"(a[3]), "r"(b[0]), "r"(b[1]));
}

// ---------------------------------------------------------------- conversions
__global__ void conv16_kernel(const float* __restrict__ in, __half* __restrict__ out, int n4) {
    int i = blockIdx.x * blockDim.x + threadIdx.x;
    if (i >= n4) return;
    float4 v = __ldg((const float4*)in + i);
    __half2 h0 = __floats2half2_rn(v.x, v.y);
    __half2 h1 = __floats2half2_rn(v.z, v.w);
    uint2 o;
    o.x = *(uint32_t*)&h0;
    o.y = *(uint32_t*)&h1;
    ((uint2*)out)[i] = o;
}

// transpose+convert 4 weight matrices [k][n] fp32 -> [n][k] fp16
__global__ void wconv_kernel(const float* __restrict__ W1s, const float* __restrict__ W1n,
                             const float* __restrict__ W2s, const float* __restrict__ W2n) {
    int t = blockIdx.x * blockDim.x + threadIdx.x;   // 0 .. 4*16384-1
    int m = t >> 14;                                  // matrix
    int i = t & 16383;
    int n = i >> 7, k = i & 127;
    const float* W = (m == 0) ? W1s : (m == 1) ? W1n : (m == 2) ? W2s : W2n;
    g_w16[m][i] = __float2half_rn(__ldg(W + k * D + n));
}

// ---------------------------------------------------------------- CSR build
__global__ void zero_cnt_kernel(int* __restrict__ cnt, int n) {
    int i = blockIdx.x * blockDim.x + threadIdx.x;
    if (i < n) cnt[i] = 0;
}

__global__ void hist_kernel(const int* __restrict__ dst, int* __restrict__ cnt, int E) {
    int i = blockIdx.x * blockDim.x + threadIdx.x;
    if (i < E) atomicAdd(&cnt[dst[i]], 1);
}

__global__ void scan_kernel(const int* __restrict__ cnt, int* __restrict__ rowstart,
                            int* __restrict__ cursor, int n) {
    __shared__ int sums[1024];
    int tid = threadIdx.x;
    int per = (n + 1023) / 1024;
    int beg = tid * per;
    int end = min(beg + per, n);
    int s = 0;
    for (int i = beg; i < end; i++) s += cnt[i];
    sums[tid] = s;
    __syncthreads();
#pragma unroll
    for (int off = 1; off < 1024; off <<= 1) {
        int t = (tid >= off) ? sums[tid - off] : 0;
        __syncthreads();
        sums[tid] += t;
        __syncthreads();
    }
    int run = sums[tid] - s;
    for (int i = beg; i < end; i++) {
        rowstart[i] = run;
        cursor[i] = run;
        run += cnt[i];
    }
    if (tid == 1023) rowstart[n] = sums[1023];
}

__global__ void fill_kernel(const int* __restrict__ src, const int* __restrict__ dst,
                            int* __restrict__ cursor, int* __restrict__ csrsrc, int E) {
    int i = blockIdx.x * blockDim.x + threadIdx.x;
    if (i < E) {
        int pos = atomicAdd(&cursor[dst[i]], 1);
        csrsrc[pos] = src[i];
    }
}

// ---------------------------------------------------------------- aggregation (fp16)
__global__ void gather16_kernel(const __half* __restrict__ H, const int* __restrict__ rowstart,
                                const int* __restrict__ csrsrc, __half* __restrict__ agg, int N) {
    int w = (blockIdx.x * blockDim.x + threadIdx.x) >> 5;
    int lane = threadIdx.x & 31;
    if (w >= N) return;
    int beg = __ldg(rowstart + w);
    int end = __ldg(rowstart + w + 1);
    float2 s0 = make_float2(0.f, 0.f), s1 = make_float2(0.f, 0.f);
    float2 t0 = make_float2(0.f, 0.f), t1 = make_float2(0.f, 0.f);
    int i = beg;
    for (; i + 1 < end; i += 2) {
        int e0 = __ldg(csrsrc + i);
        int e1 = __ldg(csrsrc + i + 1);
        uint2 v0 = __ldg((const uint2*)(H + (size_t)e0 * D) + lane);
        uint2 v1 = __ldg((const uint2*)(H + (size_t)e1 * D) + lane);
        float2 a = __half22float2(*(__half2*)&v0.x);
        float2 b = __half22float2(*(__half2*)&v0.y);
        s0.x += a.x; s0.y += a.y; s1.x += b.x; s1.y += b.y;
        float2 c = __half22float2(*(__half2*)&v1.x);
        float2 d = __half22float2(*(__half2*)&v1.y);
        t0.x += c.x; t0.y += c.y; t1.x += d.x; t1.y += d.y;
    }
    if (i < end) {
        int e0 = __ldg(csrsrc + i);
        uint2 v0 = __ldg((const uint2*)(H + (size_t)e0 * D) + lane);
        float2 a = __half22float2(*(__half2*)&v0.x);
        float2 b = __half22float2(*(__half2*)&v0.y);
        s0.x += a.x; s0.y += a.y; s1.x += b.x; s1.y += b.y;
    }
    float inv = 1.0f / (float)max(end - beg, 1);
    __half2 o0 = __floats2half2_rn((s0.x + t0.x) * inv, (s0.y + t0.y) * inv);
    __half2 o1 = __floats2half2_rn((s1.x + t1.x) * inv, (s1.y + t1.y) * inv);
    uint2 o;
    o.x = *(uint32_t*)&o0;
    o.y = *(uint32_t*)&o1;
    *((uint2*)(agg + (size_t)w * D) + lane) = o;
}

// ---------------------------------------------------------------- fp16 mma GEMM
// out = relu?( Aself @ Wself + Aagg @ Wneigh + bias ); mode1: fused classifier.
// CTA 128x128, 8 warps 4(m)x2(n), warp 32x64 = 2 mtiles x 8 ntiles of m16n8k16.
// SMEM (halves, 64 B rows = four 16 B vectors), swizzle v' = v ^ ((r>>1)&3):
// conflict-free for producer STS.128 and all fragment LDS (verified by bank enum).
__global__ void __launch_bounds__(256, 2)
gemm_sage_f16(const __half* __restrict__ Aself, const __half* __restrict__ Aagg,
              const __half* __restrict__ Wself, const __half* __restrict__ Wneigh,
              const float* __restrict__ bias, __half* __restrict__ out, int M, int mode,
              const float* __restrict__ Wc, const float* __restrict__ bc,
              float* __restrict__ out2) {
    __shared__ __align__(16) uint32_t As[128 * 16];  // 128 rows x 32 halves (8 KB)
    __shared__ __align__(16) uint32_t Bs[128 * 16];  // 128 n-rows x 32 k-halves (8 KB)
    __shared__ float s_cls[2][128][2];

    int tid = threadIdx.x;
    int wid = tid >> 5;
    int lane = tid & 31;
    int wm = wid >> 1;
    int wn = wid & 1;
    int row0 = blockIdx.x * 128;

    float acc[2][8][4];
#pragma unroll
    for (int mt = 0; mt < 2; mt++)
#pragma unroll
        for (int nt = 0; nt < 8; nt++)
#pragma unroll
            for (int e = 0; e < 4; e++) acc[mt][nt][e] = 0.f;

    // consumer maps
    int r0l = wm * 32 + (lane >> 2);
    int wlo = lane & 3;                // word offset within 16B vector
    int n_row = wn * 64 + (lane >> 2); // + nt*8

#pragma unroll 1
    for (int phase = 0; phase < 2; ++phase) {
        const __half* A = phase ? Aagg : Aself;
        const __half* W = phase ? Wneigh : Wself;
#pragma unroll 1
        for (int kc = 0; kc < 4; ++kc) {
            int k0 = kc * 32;
            __syncthreads();
            // stage A + B: i in {tid, tid+256}; r = i>>2, v = i&3
#pragma unroll
            for (int it = 0; it < 2; it++) {
                int i = tid + it * 256;
                int r = i >> 2, v = i & 3;
                int gr = min(row0 + r, M - 1);
                uint4 ta = __ldg((const uint4*)(A + (size_t)gr * D + k0 + v * 8));
                ((uint4*)As)[r * 4 + (v ^ ((r >> 1) & 3))] = ta;
                uint4 tb = __ldg((const uint4*)(W + (size_t)r * D + k0 + v * 8));
                ((uint4*)Bs)[r * 4 + (v ^ ((r >> 1) & 3))] = tb;
            }
            __syncthreads();
            // compute: 2 k16 steps
#pragma unroll
            for (int ks = 0; ks < 2; ks++) {
                uint32_t af[2][4];
#pragma unroll
                for (int mt = 0; mt < 2; mt++) {
                    int r = r0l + mt * 16;
                    int sw = (r >> 1) & 3;
                    int v0 = (2 * ks) ^ sw, v1 = (2 * ks + 1) ^ sw;
                    af[mt][0] = As[r * 16 + v0 * 4 + wlo];
                    af[mt][1] = As[(r + 8) * 16 + v0 * 4 + wlo];
                    af[mt][2] = As[r * 16 + v1 * 4 + wlo];
                    af[mt][3] = As[(r + 8) * 16 + v1 * 4 + wlo];
                }
#pragma unroll
                for (int nt = 0; nt < 8; nt++) {
                    int n = n_row + nt * 8;
                    int swn = (n >> 1) & 3;
                    uint32_t b2[2];
                    b2[0] = Bs[n * 16 + ((2 * ks) ^ swn) * 4 + wlo];
                    b2[1] = Bs[n * 16 + ((2 * ks + 1) ^ swn) * 4 + wlo];
#pragma unroll
                    for (int mt = 0; mt < 2; mt++)
                        mma_f16(acc[mt][nt], af[mt], b2);
                }
            }
        }
    }

    // ---------------- epilogue ----------------
    if (mode == 0) {
#pragma unroll
        for (int mt = 0; mt < 2; mt++) {
            int r = row0 + wm * 32 + mt * 16 + (lane >> 2);
#pragma unroll
            for (int nt = 0; nt < 8; nt++) {
                int c = wn * 64 + nt * 8 + (lane & 3) * 2;
                float b0 = __ldg(bias + c), b1 = __ldg(bias + c + 1);
                if (r < M) {
                    __half2 o = __floats2half2_rn(fmaxf(acc[mt][nt][0] + b0, 0.f),
                                                  fmaxf(acc[mt][nt][1] + b1, 0.f));
                    *(__half2*)(out + (size_t)r * D + c) = o;
                }
                if (r + 8 < M) {
                    __half2 o = __floats2half2_rn(fmaxf(acc[mt][nt][2] + b0, 0.f),
                                                  fmaxf(acc[mt][nt][3] + b1, 0.f));
                    *(__half2*)(out + (size_t)(r + 8) * D + c) = o;
                }
            }
        }
    } else {
#pragma unroll
        for (int mt = 0; mt < 2; mt++) {
            float p00 = 0.f, p01 = 0.f, p10 = 0.f, p11 = 0.f;
#pragma unroll
            for (int nt = 0; nt < 8; nt++) {
                int c = wn * 64 + nt * 8 + (lane & 3) * 2;
                float b0 = __ldg(bias + c), b1 = __ldg(bias + c + 1);
                float2 w0 = __ldg((const float2*)(Wc + (size_t)c * 2));
                float2 w1 = __ldg((const float2*)(Wc + (size_t)(c + 1) * 2));
                float h0 = acc[mt][nt][0] + b0, h1 = acc[mt][nt][1] + b1;
                float h2 = acc[mt][nt][2] + b0, h3 = acc[mt][nt][3] + b1;
                p00 += h0 * w0.x + h1 * w1.x;
                p01 += h0 * w0.y + h1 * w1.y;
                p10 += h2 * w0.x + h3 * w1.x;
                p11 += h2 * w0.y + h3 * w1.y;
            }
#pragma unroll
            for (int off = 1; off <= 2; off <<= 1) {
                p00 += __shfl_xor_sync(0xFFFFFFFFu, p00, off);
                p01 += __shfl_xor_sync(0xFFFFFFFFu, p01, off);
                p10 += __shfl_xor_sync(0xFFFFFFFFu, p10, off);
                p11 += __shfl_xor_sync(0xFFFFFFFFu, p11, off);
            }
            if ((lane & 3) == 0) {
                int lr = wm * 32 + mt * 16 + (lane >> 2);
                s_cls[wn][lr][0] = p00;
                s_cls[wn][lr][1] = p01;
                s_cls[wn][lr + 8][0] = p10;
                s_cls[wn][lr + 8][1] = p11;
            }
        }
        __syncthreads();
        {
            int row = tid >> 1;
            int j = tid & 1;
            if (row0 + row < M) {
                float v = s_cls[0][row][j] + s_cls[1][row][j] + __ldg(bc + j);
                out2[(size_t)(row0 + row) * 2 + j] = v;
            }
        }
    }
}

// ---------------------------------------------------------------- launch
extern "C" void kernel_launch(void* const* d_in, const int* in_sizes, int n_in,
                              void* d_out, int out_size) {
    const float* features = (const float*)d_in[0];
    const int*   src      = (const int*)d_in[1];
    const int*   dst      = (const int*)d_in[2];
    const float* W1s      = (const float*)d_in[3];
    const float* W1n      = (const float*)d_in[4];
    const float* b1       = (const float*)d_in[5];
    const float* W2s      = (const float*)d_in[6];
    const float* W2n      = (const float*)d_in[7];
    const float* b2       = (const float*)d_in[8];
    const float* Wc       = (const float*)d_in[9];
    const float* bc       = (const float*)d_in[10];

    int N = in_sizes[0] / D;
    int E = in_sizes[1];

    int *cnt, *cursor, *rowstart, *csrsrc;
    __half *feat16, *agg16, *h116, *w16;
    cudaGetSymbolAddress((void**)&cnt, g_cnt);
    cudaGetSymbolAddress((void**)&cursor, g_cursor);
    cudaGetSymbolAddress((void**)&rowstart, g_rowstart);
    cudaGetSymbolAddress((void**)&csrsrc, g_csrsrc);
    cudaGetSymbolAddress((void**)&feat16, g_feat16);
    cudaGetSymbolAddress((void**)&agg16, g_agg16);
    cudaGetSymbolAddress((void**)&h116, g_h116);
    cudaGetSymbolAddress((void**)&w16, g_w16);

    int mblocks = (N + 127) / 128;
    int gblocks = (N + 7) / 8;
    int n4 = N * (D / 4);

    zero_cnt_kernel<<<(N + 255) / 256, 256>>>(cnt, N);                    // 0
    hist_kernel<<<(E + 255) / 256, 256>>>(dst, cnt, E);                   // 1
    scan_kernel<<<1, 1024>>>(cnt, rowstart, cursor, N);                   // 2
    fill_kernel<<<(E + 255) / 256, 256>>>(src, dst, cursor, csrsrc, E);   // 3
    conv16_kernel<<<(n4 + 255) / 256, 256>>>(features, feat16, n4);       // 4
    gather16_kernel<<<gblocks, 256>>>(feat16, rowstart, csrsrc, agg16, N);// 5 (profiled)
    wconv_kernel<<<(4 * D * D + 255) / 256, 256>>>(W1s, W1n, W2s, W2n);   // 6

    gemm_sage_f16<<<mblocks, 256>>>(feat16, agg16, w16, w16 + D * D,
                                    b1, h116, N, 0, nullptr, nullptr, nullptr);
    gather16_kernel<<<gblocks, 256>>>(h116, rowstart, csrsrc, agg16, N);
    gemm_sage_f16<<<mblocks, 256>>>(h116, agg16, w16 + 2 * D * D, w16 + 3 * D * D,
                                    b2, nullptr, N, 1, Wc, bc, (float*)d_out);
}

// round 8
// speedup vs baseline: 1.8651x; 1.0172x over previous
#include <cuda_runtime.h>
#include <cuda_fp16.h>
#include <cstdint>

#define N_NODES 100000
#define N_EDGES 1600000
#define D 128

// Scratch (allocation-free: __device__ globals)
__device__ int    g_cnt[N_NODES];
__device__ int    g_cursor[N_NODES];
__device__ int    g_rowstart[N_NODES + 1];
__device__ int    g_csrsrc[N_EDGES];
__device__ __align__(128) __half g_feat16[(size_t)N_NODES * D];
__device__ __align__(128) __half g_agg16[(size_t)N_NODES * D];
__device__ __align__(128) __half g_h116[(size_t)N_NODES * D];
__device__ __align__(128) __half g_w16[4][D * D];  // n-major transposed weights

// ---------------------------------------------------------------- helpers
__device__ __forceinline__ void mma_f16(float* d, const uint32_t* a, const uint32_t* b) {
    asm volatile(
        "mma.sync.aligned.m16n8k16.row.col.f32.f16.f16.f32 "
        "{%0,%1,%2,%3}, {%4,%5,%6,%7}, {%8,%9}, {%0,%1,%2,%3};"
        : "+f"(d[0]), "+f"(d[1]), "+f"(d[2]), "+f"(d[3])
        : "r"(a[0]), "r"(a[1]), "r"(a[2]), "r"(a[3]), "r"(b[0]), "r"(b[1]));
}
__device__ __forceinline__ void cp16(uint32_t dst, const void* src) {
    asm volatile("cp.async.cg.shared.global [%0], [%1], 16;" :: "r"(dst), "l"(src));
}
#define CP_COMMIT() asm volatile("cp.async.commit_group;" ::: "memory")
#define CP_WAIT(n)  asm volatile("cp.async.wait_group %0;" :: "n"(n) : "memory")

// ---------------------------------------------------------------- conversions
__global__ void conv16_kernel(const float* __restrict__ in, __half* __restrict__ out, int n4) {
    int i = blockIdx.x * blockDim.x + threadIdx.x;
    if (i >= n4) return;
    float4 v = __ldg((const float4*)in + i);
    __half2 h0 = __floats2half2_rn(v.x, v.y);
    __half2 h1 = __floats2half2_rn(v.z, v.w);
    uint2 o;
    o.x = *(uint32_t*)&h0;
    o.y = *(uint32_t*)&h1;
    ((uint2*)out)[i] = o;
}

// transpose+convert 4 weight matrices [k][n] fp32 -> [n][k] fp16
__global__ void wconv_kernel(const float* __restrict__ W1s, const float* __restrict__ W1n,
                             const float* __restrict__ W2s, const float* __restrict__ W2n) {
    int t = blockIdx.x * blockDim.x + threadIdx.x;
    int m = t >> 14;
    int i = t & 16383;
    int n = i >> 7, k = i & 127;
    const float* W = (m == 0) ? W1s : (m == 1) ? W1n : (m == 2) ? W2s : W2n;
    g_w16[m][i] = __float2half_rn(__ldg(W + k * D + n));
}

// ---------------------------------------------------------------- CSR build
__global__ void zero_cnt_kernel(int* __restrict__ cnt, int n) {
    int i = blockIdx.x * blockDim.x + threadIdx.x;
    if (i < n) cnt[i] = 0;
}

__global__ void hist_kernel(const int* __restrict__ dst, int* __restrict__ cnt, int E) {
    int i = blockIdx.x * blockDim.x + threadIdx.x;
    if (i < E) atomicAdd(&cnt[dst[i]], 1);
}

__global__ void scan_kernel(const int* __restrict__ cnt, int* __restrict__ rowstart,
                            int* __restrict__ cursor, int n) {
    __shared__ int sums[1024];
    int tid = threadIdx.x;
    int per = (n + 1023) / 1024;
    int beg = tid * per;
    int end = min(beg + per, n);
    int s = 0;
    for (int i = beg; i < end; i++) s += cnt[i];
    sums[tid] = s;
    __syncthreads();
#pragma unroll
    for (int off = 1; off < 1024; off <<= 1) {
        int t = (tid >= off) ? sums[tid - off] : 0;
        __syncthreads();
        sums[tid] += t;
        __syncthreads();
    }
    int run = sums[tid] - s;
    for (int i = beg; i < end; i++) {
        rowstart[i] = run;
        cursor[i] = run;
        run += cnt[i];
    }
    if (tid == 1023) rowstart[n] = sums[1023];
}

__global__ void fill_kernel(const int* __restrict__ src, const int* __restrict__ dst,
                            int* __restrict__ cursor, int* __restrict__ csrsrc, int E) {
    int i = blockIdx.x * blockDim.x + threadIdx.x;
    if (i < E) {
        int pos = atomicAdd(&cursor[dst[i]], 1);
        csrsrc[pos] = src[i];
    }
}

// ---------------------------------------------------------------- aggregation (fp16)
__global__ void gather16_kernel(const __half* __restrict__ H, const int* __restrict__ rowstart,
                                const int* __restrict__ csrsrc, __half* __restrict__ agg, int N) {
    int w = (blockIdx.x * blockDim.x + threadIdx.x) >> 5;
    int lane = threadIdx.x & 31;
    if (w >= N) return;
    int beg = __ldg(rowstart + w);
    int end = __ldg(rowstart + w + 1);
    float2 s0 = make_float2(0.f, 0.f), s1 = make_float2(0.f, 0.f);
    float2 t0 = make_float2(0.f, 0.f), t1 = make_float2(0.f, 0.f);
    int i = beg;
    for (; i + 1 < end; i += 2) {
        int e0 = __ldg(csrsrc + i);
        int e1 = __ldg(csrsrc + i + 1);
        uint2 v0 = __ldg((const uint2*)(H + (size_t)e0 * D) + lane);
        uint2 v1 = __ldg((const uint2*)(H + (size_t)e1 * D) + lane);
        float2 a = __half22float2(*(__half2*)&v0.x);
        float2 b = __half22float2(*(__half2*)&v0.y);
        s0.x += a.x; s0.y += a.y; s1.x += b.x; s1.y += b.y;
        float2 c = __half22float2(*(__half2*)&v1.x);
        float2 d = __half22float2(*(__half2*)&v1.y);
        t0.x += c.x; t0.y += c.y; t1.x += d.x; t1.y += d.y;
    }
    if (i < end) {
        int e0 = __ldg(csrsrc + i);
        uint2 v0 = __ldg((const uint2*)(H + (size_t)e0 * D) + lane);
        float2 a = __half22float2(*(__half2*)&v0.x);
        float2 b = __half22float2(*(__half2*)&v0.y);
        s0.x += a.x; s0.y += a.y; s1.x += b.x; s1.y += b.y;
    }
    float inv = 1.0f / (float)max(end - beg, 1);
    __half2 o0 = __floats2half2_rn((s0.x + t0.x) * inv, (s0.y + t0.y) * inv);
    __half2 o1 = __floats2half2_rn((s1.x + t1.x) * inv, (s1.y + t1.y) * inv);
    uint2 o;
    o.x = *(uint32_t*)&o0;
    o.y = *(uint32_t*)&o1;
    *((uint2*)(agg + (size_t)w * D) + lane) = o;
}

// ---------------------------------------------------------------- fp16 mma GEMM
// Double-buffered cp.async mainloop. K chunks of 64 halves (128 B rows).
// SMEM swizzle: 16B-vector index v' = v ^ (r & 7)  (conflict-free producer + consumer).
// Dynamic SMEM: As[2][128*32] Bs[2][128*32] words = 64 KB.
#define CHUNK_WORDS (128 * 32)
__global__ void __launch_bounds__(256, 2)
gemm_sage_f16(const __half* __restrict__ Aself, const __half* __restrict__ Aagg,
              const __half* __restrict__ Wself, const __half* __restrict__ Wneigh,
              const float* __restrict__ bias, __half* __restrict__ out, int M, int mode,
              const float* __restrict__ Wc, const float* __restrict__ bc,
              float* __restrict__ out2) {
    extern __shared__ __align__(16) uint32_t dyn[];
    uint32_t* Abuf[2] = {dyn, dyn + CHUNK_WORDS};
    uint32_t* Bbuf[2] = {dyn + 2 * CHUNK_WORDS, dyn + 3 * CHUNK_WORDS};
    __shared__ float s_cls[2][128][2];

    int tid = threadIdx.x;
    int wid = tid >> 5;
    int lane = tid & 31;
    int wm = wid >> 1;
    int wn = wid & 1;
    int row0 = blockIdx.x * 128;

    const __half* Aarr[2] = {Aself, Aagg};
    const __half* Warr[2] = {Wself, Wneigh};

    float acc[2][8][4];
#pragma unroll
    for (int mt = 0; mt < 2; mt++)
#pragma unroll
        for (int nt = 0; nt < 8; nt++)
#pragma unroll
            for (int e = 0; e < 4; e++) acc[mt][nt][e] = 0.f;

    // staging map: i = tid + it*256 -> r = i>>3 (0..127), v = i&7
    int s_r = tid >> 3;
    int s_v = tid & 7;
    uint32_t a_sm[2], b_sm[2];
#pragma unroll
    for (int b = 0; b < 2; b++) {
        a_sm[b] = (uint32_t)__cvta_generic_to_shared(Abuf[b]);
        b_sm[b] = (uint32_t)__cvta_generic_to_shared(Bbuf[b]);
    }

    // consumer maps
    int r0l = wm * 32 + (lane >> 2);
    int wlo = lane & 3;
    int n_row = wn * 64 + (lane >> 2);

    // ---- stage step 0 ----
    {
        const __half* A = Aarr[0];
        const __half* W = Warr[0];
#pragma unroll
        for (int it = 0; it < 4; it++) {
            int r = s_r + it * 32;
            int gr = min(row0 + r, M - 1);
            uint32_t off = (uint32_t)((r * 8 + (s_v ^ (r & 7))) * 16);
            cp16(a_sm[0] + off, A + (size_t)gr * D + s_v * 8);
            cp16(b_sm[0] + off, W + (size_t)r * D + s_v * 8);
        }
        CP_COMMIT();
    }

#pragma unroll 1
    for (int step = 0; step < 4; ++step) {
        // prefetch next chunk
        if (step < 3) {
            int ns = step + 1;
            const __half* A = Aarr[ns >> 1];
            const __half* W = Warr[ns >> 1];
            int k0 = (ns & 1) * 64;
            int nb = ns & 1;
#pragma unroll
            for (int it = 0; it < 4; it++) {
                int r = s_r + it * 32;
                int gr = min(row0 + r, M - 1);
                uint32_t off = (uint32_t)((r * 8 + (s_v ^ (r & 7))) * 16);
                cp16(a_sm[nb] + off, A + (size_t)gr * D + k0 + s_v * 8);
                cp16(b_sm[nb] + off, W + (size_t)r * D + k0 + s_v * 8);
            }
            CP_COMMIT();
            CP_WAIT(1);
        } else {
            CP_WAIT(0);
        }
        __syncthreads();

        const uint32_t* As = Abuf[step & 1];
        const uint32_t* Bs = Bbuf[step & 1];
#pragma unroll
        for (int ks = 0; ks < 4; ks++) {
            uint32_t af[2][4];
#pragma unroll
            for (int mt = 0; mt < 2; mt++) {
                int r = r0l + mt * 16;
                int sw = r & 7;
                int v0 = (2 * ks) ^ sw, v1 = (2 * ks + 1) ^ sw;
                af[mt][0] = As[r * 32 + v0 * 4 + wlo];
                af[mt][1] = As[(r + 8) * 32 + v0 * 4 + wlo];
                af[mt][2] = As[r * 32 + v1 * 4 + wlo];
                af[mt][3] = As[(r + 8) * 32 + v1 * 4 + wlo];
            }
#pragma unroll
            for (int nt = 0; nt < 8; nt++) {
                int n = n_row + nt * 8;
                int swn = n & 7;
                uint32_t b2[2];
                b2[0] = Bs[n * 32 + ((2 * ks) ^ swn) * 4 + wlo];
                b2[1] = Bs[n * 32 + ((2 * ks + 1) ^ swn) * 4 + wlo];
#pragma unroll
                for (int mt = 0; mt < 2; mt++)
                    mma_f16(acc[mt][nt], af[mt], b2);
            }
        }
        __syncthreads();
    }

    // ---------------- epilogue ----------------
    if (mode == 0) {
#pragma unroll
        for (int mt = 0; mt < 2; mt++) {
            int r = row0 + wm * 32 + mt * 16 + (lane >> 2);
#pragma unroll
            for (int nt = 0; nt < 8; nt++) {
                int c = wn * 64 + nt * 8 + (lane & 3) * 2;
                float b0 = __ldg(bias + c), b1 = __ldg(bias + c + 1);
                if (r < M) {
                    __half2 o = __floats2half2_rn(fmaxf(acc[mt][nt][0] + b0, 0.f),
                                                  fmaxf(acc[mt][nt][1] + b1, 0.f));
                    *(__half2*)(out + (size_t)r * D + c) = o;
                }
                if (r + 8 < M) {
                    __half2 o = __floats2half2_rn(fmaxf(acc[mt][nt][2] + b0, 0.f),
                                                  fmaxf(acc[mt][nt][3] + b1, 0.f));
                    *(__half2*)(out + (size_t)(r + 8) * D + c) = o;
                }
            }
        }
    } else {
#pragma unroll
        for (int mt = 0; mt < 2; mt++) {
            float p00 = 0.f, p01 = 0.f, p10 = 0.f, p11 = 0.f;
#pragma unroll
            for (int nt = 0; nt < 8; nt++) {
                int c = wn * 64 + nt * 8 + (lane & 3) * 2;
                float b0 = __ldg(bias + c), b1 = __ldg(bias + c + 1);
                float2 w0 = __ldg((const float2*)(Wc + (size_t)c * 2));
                float2 w1 = __ldg((const float2*)(Wc + (size_t)(c + 1) * 2));
                float h0 = acc[mt][nt][0] + b0, h1 = acc[mt][nt][1] + b1;
                float h2 = acc[mt][nt][2] + b0, h3 = acc[mt][nt][3] + b1;
                p00 += h0 * w0.x + h1 * w1.x;
                p01 += h0 * w0.y + h1 * w1.y;
                p10 += h2 * w0.x + h3 * w1.x;
                p11 += h2 * w0.y + h3 * w1.y;
            }
#pragma unroll
            for (int off = 1; off <= 2; off <<= 1) {
                p00 += __shfl_xor_sync(0xFFFFFFFFu, p00, off);
                p01 += __shfl_xor_sync(0xFFFFFFFFu, p01, off);
                p10 += __shfl_xor_sync(0xFFFFFFFFu, p10, off);
                p11 += __shfl_xor_sync(0xFFFFFFFFu, p11, off);
            }
            if ((lane & 3) == 0) {
                int lr = wm * 32 + mt * 16 + (lane >> 2);
                s_cls[wn][lr][0] = p00;
                s_cls[wn][lr][1] = p01;
                s_cls[wn][lr + 8][0] = p10;
                s_cls[wn][lr + 8][1] = p11;
            }
        }
        __syncthreads();
        {
            int row = tid >> 1;
            int j = tid & 1;
            if (row0 + row < M) {
                float v = s_cls[0][row][j] + s_cls[1][row][j] + __ldg(bc + j);
                out2[(size_t)(row0 + row) * 2 + j] = v;
            }
        }
    }
}

// ---------------------------------------------------------------- launch
extern "C" void kernel_launch(void* const* d_in, const int* in_sizes, int n_in,
                              void* d_out, int out_size) {
    const float* features = (const float*)d_in[0];
    const int*   src      = (const int*)d_in[1];
    const int*   dst      = (const int*)d_in[2];
    const float* W1s      = (const float*)d_in[3];
    const float* W1n      = (const float*)d_in[4];
    const float* b1       = (const float*)d_in[5];
    const float* W2s      = (const float*)d_in[6];
    const float* W2n      = (const float*)d_in[7];
    const float* b2       = (const float*)d_in[8];
    const float* Wc       = (const float*)d_in[9];
    const float* bc       = (const float*)d_in[10];

    int N = in_sizes[0] / D;
    int E = in_sizes[1];

    int *cnt, *cursor, *rowstart, *csrsrc;
    __half *feat16, *agg16, *h116, *w16;
    cudaGetSymbolAddress((void**)&cnt, g_cnt);
    cudaGetSymbolAddress((void**)&cursor, g_cursor);
    cudaGetSymbolAddress((void**)&rowstart, g_rowstart);
    cudaGetSymbolAddress((void**)&csrsrc, g_csrsrc);
    cudaGetSymbolAddress((void**)&feat16, g_feat16);
    cudaGetSymbolAddress((void**)&agg16, g_agg16);
    cudaGetSymbolAddress((void**)&h116, g_h116);
    cudaGetSymbolAddress((void**)&w16, g_w16);

    static int attr_done = 0;
    if (!attr_done) {
        cudaFuncSetAttribute(gemm_sage_f16,
                             cudaFuncAttributeMaxDynamicSharedMemorySize, 65536);
        attr_done = 1;
    }

    int mblocks = (N + 127) / 128;
    int gblocks = (N + 7) / 8;
    int n4 = N * (D / 4);
    const int SMEM = 65536;

    zero_cnt_kernel<<<(N + 255) / 256, 256>>>(cnt, N);
    hist_kernel<<<(E + 255) / 256, 256>>>(dst, cnt, E);
    scan_kernel<<<1, 1024>>>(cnt, rowstart, cursor, N);
    fill_kernel<<<(E + 255) / 256, 256>>>(src, dst, cursor, csrsrc, E);
    conv16_kernel<<<(n4 + 255) / 256, 256>>>(features, feat16, n4);
    gather16_kernel<<<gblocks, 256>>>(feat16, rowstart, csrsrc, agg16, N);
    wconv_kernel<<<(4 * D * D + 255) / 256, 256>>>(W1s, W1n, W2s, W2n);

    gemm_sage_f16<<<mblocks, 256, SMEM>>>(feat16, agg16, w16, w16 + D * D,
                                          b1, h116, N, 0, nullptr, nullptr, nullptr);
    gather16_kernel<<<gblocks, 256>>>(h116, rowstart, csrsrc, agg16, N);
    gemm_sage_f16<<<mblocks, 256, SMEM>>>(h116, agg16, w16 + 2 * D * D, w16 + 3 * D * D,
                                          b2, nullptr, N, 1, Wc, bc, (float*)d_out);
}

// round 9
// speedup vs baseline: 2.8232x; 1.5137x over previous
#include <cuda_runtime.h>
#include <cuda_fp16.h>
#include <cstdint>

#define N_NODES 100000
#define N_EDGES 1600000
#define D 128
#define SCAN_B 256

// Scratch (allocation-free: __device__ globals)
__device__ int    g_cnt[N_NODES];
__device__ int    g_cursor[N_NODES];
__device__ int    g_rowstart[N_NODES + 1];
__device__ int    g_bsum[1024];
__device__ int    g_csrsrc[N_EDGES];
__device__ __align__(128) __half g_feat16[(size_t)N_NODES * D];
__device__ __align__(128) __half g_agg16[(size_t)N_NODES * D];
__device__ __align__(128) __half g_h116[(size_t)N_NODES * D];
__device__ __align__(128) __half g_w16[4][D * D];  // n-major transposed weights

// ---------------------------------------------------------------- helpers
__device__ __forceinline__ void mma_f16(float* d, const uint32_t* a, const uint32_t* b) {
    asm volatile(
        "mma.sync.aligned.m16n8k16.row.col.f32.f16.f16.f32 "
        "{%0,%1,%2,%3}, {%4,%5,%6,%7}, {%8,%9}, {%0,%1,%2,%3};"
        : "+f"(d[0]), "+f"(d[1]), "+f"(d[2]), "+f"(d[3])
        : "r"(a[0]), "r"(a[1]), "r"(a[2]), "r"(a[3]), "r"(b[0]), "r"(b[1]));
}
__device__ __forceinline__ void cp16(uint32_t dst, const void* src) {
    asm volatile("cp.async.cg.shared.global [%0], [%1], 16;" :: "r"(dst), "l"(src));
}
#define CP_COMMIT() asm volatile("cp.async.commit_group;" ::: "memory")
#define CP_WAIT(n)  asm volatile("cp.async.wait_group %0;" :: "n"(n) : "memory")

// ---------------------------------------------------------------- conversions
__global__ void conv16_kernel(const float* __restrict__ in, __half* __restrict__ out, int n4) {
    int i = blockIdx.x * blockDim.x + threadIdx.x;
    if (i >= n4) return;
    float4 v = __ldg((const float4*)in + i);
    __half2 h0 = __floats2half2_rn(v.x, v.y);
    __half2 h1 = __floats2half2_rn(v.z, v.w);
    uint2 o;
    o.x = *(uint32_t*)&h0;
    o.y = *(uint32_t*)&h1;
    ((uint2*)out)[i] = o;
}

__global__ void wconv_kernel(const float* __restrict__ W1s, const float* __restrict__ W1n,
                             const float* __restrict__ W2s, const float* __restrict__ W2n) {
    int t = blockIdx.x * blockDim.x + threadIdx.x;
    int m = t >> 14;
    int i = t & 16383;
    int n = i >> 7, k = i & 127;
    const float* W = (m == 0) ? W1s : (m == 1) ? W1n : (m == 2) ? W2s : W2n;
    g_w16[m][i] = __float2half_rn(__ldg(W + k * D + n));
}

// ---------------------------------------------------------------- CSR build
__global__ void zero_cnt_kernel(int* __restrict__ cnt, int n) {
    int i = blockIdx.x * blockDim.x + threadIdx.x;
    if (i < n) cnt[i] = 0;
}

__global__ void hist_kernel(const int2* __restrict__ dst2, int* __restrict__ cnt, int E2) {
    int i = blockIdx.x * blockDim.x + threadIdx.x;
    if (i < E2) {
        int2 d = __ldg(dst2 + i);
        atomicAdd(&cnt[d.x], 1);
        atomicAdd(&cnt[d.y], 1);
    }
}

// parallel scan: level-1 block sums
__global__ void scan_bsum_kernel(const int* __restrict__ cnt, int* __restrict__ bsum, int n) {
    __shared__ int sh[SCAN_B];
    int i = blockIdx.x * SCAN_B + threadIdx.x;
    sh[threadIdx.x] = (i < n) ? cnt[i] : 0;
    __syncthreads();
#pragma unroll
    for (int off = SCAN_B / 2; off; off >>= 1) {
        if (threadIdx.x < off) sh[threadIdx.x] += sh[threadIdx.x + off];
        __syncthreads();
    }
    if (threadIdx.x == 0) bsum[blockIdx.x] = sh[0];
}

// level-2: exclusive-scan block sums in one block (nb <= 512)
__global__ void scan_top_kernel(int* __restrict__ bsum, int* __restrict__ rowstart,
                                int nb, int n) {
    __shared__ int sh[512];
    int t = threadIdx.x;
    int v = (t < nb) ? bsum[t] : 0;
    sh[t] = v;
    __syncthreads();
#pragma unroll
    for (int off = 1; off < 512; off <<= 1) {
        int u = (t >= off) ? sh[t - off] : 0;
        __syncthreads();
        sh[t] += u;
        __syncthreads();
    }
    if (t < nb) bsum[t] = sh[t] - v;  // exclusive
    if (t == 511) rowstart[n] = sh[511];
}

// level-3: per-block exclusive scan + offset
__global__ void scan_fin_kernel(const int* __restrict__ cnt, const int* __restrict__ bsum,
                                int* __restrict__ rowstart, int* __restrict__ cursor, int n) {
    __shared__ int sh[SCAN_B];
    int i = blockIdx.x * SCAN_B + threadIdx.x;
    int v = (i < n) ? cnt[i] : 0;
    sh[threadIdx.x] = v;
    __syncthreads();
#pragma unroll
    for (int off = 1; off < SCAN_B; off <<= 1) {
        int u = (threadIdx.x >= off) ? sh[threadIdx.x - off] : 0;
        __syncthreads();
        sh[threadIdx.x] += u;
        __syncthreads();
    }
    if (i < n) {
        int ex = sh[threadIdx.x] - v + bsum[blockIdx.x];
        rowstart[i] = ex;
        cursor[i] = ex;
    }
}

__global__ void fill_kernel(const int* __restrict__ src, const int* __restrict__ dst,
                            int* __restrict__ cursor, int* __restrict__ csrsrc, int E) {
    int i = blockIdx.x * blockDim.x + threadIdx.x;
    if (i < E) {
        int pos = atomicAdd(&cursor[dst[i]], 1);
        csrsrc[pos] = src[i];
    }
}

// ---------------------------------------------------------------- aggregation (fp16)
__global__ void gather16_kernel(const __half* __restrict__ H, const int* __restrict__ rowstart,
                                const int* __restrict__ csrsrc, __half* __restrict__ agg, int N) {
    int w = (blockIdx.x * blockDim.x + threadIdx.x) >> 5;
    int lane = threadIdx.x & 31;
    if (w >= N) return;
    int beg = __ldg(rowstart + w);
    int end = __ldg(rowstart + w + 1);
    float2 a0 = make_float2(0.f, 0.f), a1 = make_float2(0.f, 0.f);
    float2 b0 = make_float2(0.f, 0.f), b1 = make_float2(0.f, 0.f);
    float2 c0 = make_float2(0.f, 0.f), c1 = make_float2(0.f, 0.f);
    float2 d0 = make_float2(0.f, 0.f), d1 = make_float2(0.f, 0.f);
    int i = beg;
    for (; i + 3 < end; i += 4) {
        int e0 = __ldg(csrsrc + i);
        int e1 = __ldg(csrsrc + i + 1);
        int e2 = __ldg(csrsrc + i + 2);
        int e3 = __ldg(csrsrc + i + 3);
        uint2 v0 = __ldg((const uint2*)(H + (size_t)e0 * D) + lane);
        uint2 v1 = __ldg((const uint2*)(H + (size_t)e1 * D) + lane);
        uint2 v2 = __ldg((const uint2*)(H + (size_t)e2 * D) + lane);
        uint2 v3 = __ldg((const uint2*)(H + (size_t)e3 * D) + lane);
        float2 p, q;
        p = __half22float2(*(__half2*)&v0.x); q = __half22float2(*(__half2*)&v0.y);
        a0.x += p.x; a0.y += p.y; a1.x += q.x; a1.y += q.y;
        p = __half22float2(*(__half2*)&v1.x); q = __half22float2(*(__half2*)&v1.y);
        b0.x += p.x; b0.y += p.y; b1.x += q.x; b1.y += q.y;
        p = __half22float2(*(__half2*)&v2.x); q = __half22float2(*(__half2*)&v2.y);
        c0.x += p.x; c0.y += p.y; c1.x += q.x; c1.y += q.y;
        p = __half22float2(*(__half2*)&v3.x); q = __half22float2(*(__half2*)&v3.y);
        d0.x += p.x; d0.y += p.y; d1.x += q.x; d1.y += q.y;
    }
    for (; i < end; i++) {
        int e0 = __ldg(csrsrc + i);
        uint2 v0 = __ldg((const uint2*)(H + (size_t)e0 * D) + lane);
        float2 p = __half22float2(*(__half2*)&v0.x);
        float2 q = __half22float2(*(__half2*)&v0.y);
        a0.x += p.x; a0.y += p.y; a1.x += q.x; a1.y += q.y;
    }
    float inv = 1.0f / (float)max(end - beg, 1);
    __half2 o0 = __floats2half2_rn((a0.x + b0.x + c0.x + d0.x) * inv,
                                   (a0.y + b0.y + c0.y + d0.y) * inv);
    __half2 o1 = __floats2half2_rn((a1.x + b1.x + c1.x + d1.x) * inv,
                                   (a1.y + b1.y + c1.y + d1.y) * inv);
    uint2 o;
    o.x = *(uint32_t*)&o0;
    o.y = *(uint32_t*)&o1;
    *((uint2*)(agg + (size_t)w * D) + lane) = o;
}

// ---------------------------------------------------------------- fp16 mma GEMM
// Double-buffered cp.async mainloop. K chunks of 64 halves (128 B rows).
// SMEM swizzle: 16B-vector index v' = v ^ (r & 7).
#define CHUNK_WORDS (128 * 32)
__global__ void __launch_bounds__(256, 2)
gemm_sage_f16(const __half* __restrict__ Aself, const __half* __restrict__ Aagg,
              const __half* __restrict__ Wself, const __half* __restrict__ Wneigh,
              const float* __restrict__ bias, __half* __restrict__ out, int M, int mode,
              const float* __restrict__ Wc, const float* __restrict__ bc,
              float* __restrict__ out2) {
    extern __shared__ __align__(16) uint32_t dyn[];
    uint32_t* Abuf[2] = {dyn, dyn + CHUNK_WORDS};
    uint32_t* Bbuf[2] = {dyn + 2 * CHUNK_WORDS, dyn + 3 * CHUNK_WORDS};
    __shared__ float s_cls[2][128][2];

    int tid = threadIdx.x;
    int wid = tid >> 5;
    int lane = tid & 31;
    int wm = wid >> 1;
    int wn = wid & 1;
    int row0 = blockIdx.x * 128;

    const __half* Aarr[2] = {Aself, Aagg};
    const __half* Warr[2] = {Wself, Wneigh};

    float acc[2][8][4];
#pragma unroll
    for (int mt = 0; mt < 2; mt++)
#pragma unroll
        for (int nt = 0; nt < 8; nt++)
#pragma unroll
            for (int e = 0; e < 4; e++) acc[mt][nt][e] = 0.f;

    int s_r = tid >> 3;
    int s_v = tid & 7;
    uint32_t a_sm[2], b_sm[2];
#pragma unroll
    for (int b = 0; b < 2; b++) {
        a_sm[b] = (uint32_t)__cvta_generic_to_shared(Abuf[b]);
        b_sm[b] = (uint32_t)__cvta_generic_to_shared(Bbuf[b]);
    }

    int r0l = wm * 32 + (lane >> 2);
    int wlo = lane & 3;
    int n_row = wn * 64 + (lane >> 2);

    {
        const __half* A = Aarr[0];
        const __half* W = Warr[0];
#pragma unroll
        for (int it = 0; it < 4; it++) {
            int r = s_r + it * 32;
            int gr = min(row0 + r, M - 1);
            uint32_t off = (uint32_t)((r * 8 + (s_v ^ (r & 7))) * 16);
            cp16(a_sm[0] + off, A + (size_t)gr * D + s_v * 8);
            cp16(b_sm[0] + off, W + (size_t)r * D + s_v * 8);
        }
        CP_COMMIT();
    }

#pragma unroll 1
    for (int step = 0; step < 4; ++step) {
        if (step < 3) {
            int ns = step + 1;
            const __half* A = Aarr[ns >> 1];
            const __half* W = Warr[ns >> 1];
            int k0 = (ns & 1) * 64;
            int nb = ns & 1;
#pragma unroll
            for (int it = 0; it < 4; it++) {
                int r = s_r + it * 32;
                int gr = min(row0 + r, M - 1);
                uint32_t off = (uint32_t)((r * 8 + (s_v ^ (r & 7))) * 16);
                cp16(a_sm[nb] + off, A + (size_t)gr * D + k0 + s_v * 8);
                cp16(b_sm[nb] + off, W + (size_t)r * D + k0 + s_v * 8);
            }
            CP_COMMIT();
            CP_WAIT(1);
        } else {
            CP_WAIT(0);
        }
        __syncthreads();

        const uint32_t* As = Abuf[step & 1];
        const uint32_t* Bs = Bbuf[step & 1];
#pragma unroll
        for (int ks = 0; ks < 4; ks++) {
            uint32_t af[2][4];
#pragma unroll
            for (int mt = 0; mt < 2; mt++) {
                int r = r0l + mt * 16;
                int sw = r & 7;
                int v0 = (2 * ks) ^ sw, v1 = (2 * ks + 1) ^ sw;
                af[mt][0] = As[r * 32 + v0 * 4 + wlo];
                af[mt][1] = As[(r + 8) * 32 + v0 * 4 + wlo];
                af[mt][2] = As[r * 32 + v1 * 4 + wlo];
                af[mt][3] = As[(r + 8) * 32 + v1 * 4 + wlo];
            }
#pragma unroll
            for (int nt = 0; nt < 8; nt++) {
                int n = n_row + nt * 8;
                int swn = n & 7;
                uint32_t b2[2];
                b2[0] = Bs[n * 32 + ((2 * ks) ^ swn) * 4 + wlo];
                b2[1] = Bs[n * 32 + ((2 * ks + 1) ^ swn) * 4 + wlo];
#pragma unroll
                for (int mt = 0; mt < 2; mt++)
                    mma_f16(acc[mt][nt], af[mt], b2);
            }
        }
        __syncthreads();
    }

    if (mode == 0) {
#pragma unroll
        for (int mt = 0; mt < 2; mt++) {
            int r = row0 + wm * 32 + mt * 16 + (lane >> 2);
#pragma unroll
            for (int nt = 0; nt < 8; nt++) {
                int c = wn * 64 + nt * 8 + (lane & 3) * 2;
                float b0 = __ldg(bias + c), b1 = __ldg(bias + c + 1);
                if (r < M) {
                    __half2 o = __floats2half2_rn(fmaxf(acc[mt][nt][0] + b0, 0.f),
                                                  fmaxf(acc[mt][nt][1] + b1, 0.f));
                    *(__half2*)(out + (size_t)r * D + c) = o;
                }
                if (r + 8 < M) {
                    __half2 o = __floats2half2_rn(fmaxf(acc[mt][nt][2] + b0, 0.f),
                                                  fmaxf(acc[mt][nt][3] + b1, 0.f));
                    *(__half2*)(out + (size_t)(r + 8) * D + c) = o;
                }
            }
        }
    } else {
#pragma unroll
        for (int mt = 0; mt < 2; mt++) {
            float p00 = 0.f, p01 = 0.f, p10 = 0.f, p11 = 0.f;
#pragma unroll
            for (int nt = 0; nt < 8; nt++) {
                int c = wn * 64 + nt * 8 + (lane & 3) * 2;
                float b0 = __ldg(bias + c), b1 = __ldg(bias + c + 1);
                float2 w0 = __ldg((const float2*)(Wc + (size_t)c * 2));
                float2 w1 = __ldg((const float2*)(Wc + (size_t)(c + 1) * 2));
                float h0 = acc[mt][nt][0] + b0, h1 = acc[mt][nt][1] + b1;
                float h2 = acc[mt][nt][2] + b0, h3 = acc[mt][nt][3] + b1;
                p00 += h0 * w0.x + h1 * w1.x;
                p01 += h0 * w0.y + h1 * w1.y;
                p10 += h2 * w0.x + h3 * w1.x;
                p11 += h2 * w0.y + h3 * w1.y;
            }
#pragma unroll
            for (int off = 1; off <= 2; off <<= 1) {
                p00 += __shfl_xor_sync(0xFFFFFFFFu, p00, off);
                p01 += __shfl_xor_sync(0xFFFFFFFFu, p01, off);
                p10 += __shfl_xor_sync(0xFFFFFFFFu, p10, off);
                p11 += __shfl_xor_sync(0xFFFFFFFFu, p11, off);
            }
            if ((lane & 3) == 0) {
                int lr = wm * 32 + mt * 16 + (lane >> 2);
                s_cls[wn][lr][0] = p00;
                s_cls[wn][lr][1] = p01;
                s_cls[wn][lr + 8][0] = p10;
                s_cls[wn][lr + 8][1] = p11;
            }
        }
        __syncthreads();
        {
            int row = tid >> 1;
            int j = tid & 1;
            if (row0 + row < M) {
                float v = s_cls[0][row][j] + s_cls[1][row][j] + __ldg(bc + j);
                out2[(size_t)(row0 + row) * 2 + j] = v;
            }
        }
    }
}

// ---------------------------------------------------------------- launch
extern "C" void kernel_launch(void* const* d_in, const int* in_sizes, int n_in,
                              void* d_out, int out_size) {
    const float* features = (const float*)d_in[0];
    const int*   src      = (const int*)d_in[1];
    const int*   dst      = (const int*)d_in[2];
    const float* W1s      = (const float*)d_in[3];
    const float* W1n      = (const float*)d_in[4];
    const float* b1       = (const float*)d_in[5];
    const float* W2s      = (const float*)d_in[6];
    const float* W2n      = (const float*)d_in[7];
    const float* b2       = (const float*)d_in[8];
    const float* Wc       = (const float*)d_in[9];
    const float* bc       = (const float*)d_in[10];

    int N = in_sizes[0] / D;
    int E = in_sizes[1];

    int *cnt, *cursor, *rowstart, *csrsrc, *bsum;
    __half *feat16, *agg16, *h116, *w16;
    cudaGetSymbolAddress((void**)&cnt, g_cnt);
    cudaGetSymbolAddress((void**)&cursor, g_cursor);
    cudaGetSymbolAddress((void**)&rowstart, g_rowstart);
    cudaGetSymbolAddress((void**)&csrsrc, g_csrsrc);
    cudaGetSymbolAddress((void**)&bsum, g_bsum);
    cudaGetSymbolAddress((void**)&feat16, g_feat16);
    cudaGetSymbolAddress((void**)&agg16, g_agg16);
    cudaGetSymbolAddress((void**)&h116, g_h116);
    cudaGetSymbolAddress((void**)&w16, g_w16);

    static cudaStream_t s1 = nullptr;
    static cudaEvent_t ev0 = nullptr, ev1 = nullptr;
    static int init_done = 0;
    if (!init_done) {
        cudaFuncSetAttribute(gemm_sage_f16,
                             cudaFuncAttributeMaxDynamicSharedMemorySize, 65536);
        if (cudaStreamCreateWithFlags(&s1, cudaStreamNonBlocking) != cudaSuccess) s1 = nullptr;
        if (s1) {
            cudaEventCreateWithFlags(&ev0, cudaEventDisableTiming);
            cudaEventCreateWithFlags(&ev1, cudaEventDisableTiming);
        }
        init_done = 1;
    }

    int mblocks = (N + 127) / 128;
    int gblocks = (N + 7) / 8;
    int n4 = N * (D / 4);
    int nb = (N + SCAN_B - 1) / SCAN_B;   // 391
    const int SMEM = 65536;

    // fork: conversions on side stream, CSR chain on main stream
    cudaStream_t cs = s1 ? s1 : (cudaStream_t)0;
    if (s1) {
        cudaEventRecord(ev0, 0);
        cudaStreamWaitEvent(s1, ev0, 0);
    }
    conv16_kernel<<<(n4 + 255) / 256, 256, 0, cs>>>(features, feat16, n4);
    wconv_kernel<<<(4 * D * D + 255) / 256, 256, 0, cs>>>(W1s, W1n, W2s, W2n);
    if (s1) cudaEventRecord(ev1, s1);

    zero_cnt_kernel<<<(N + 255) / 256, 256>>>(cnt, N);
    hist_kernel<<<(E / 2 + 255) / 256, 256>>>((const int2*)dst, cnt, E / 2);
    scan_bsum_kernel<<<nb, SCAN_B>>>(cnt, bsum, N);
    scan_top_kernel<<<1, 512>>>(bsum, rowstart, nb, N);
    scan_fin_kernel<<<nb, SCAN_B>>>(cnt, bsum, rowstart, cursor, N);
    fill_kernel<<<(E + 255) / 256, 256>>>(src, dst, cursor, csrsrc, E);

    if (s1) cudaStreamWaitEvent((cudaStream_t)0, ev1, 0);  // join conversions

    gather16_kernel<<<gblocks, 256>>>(feat16, rowstart, csrsrc, agg16, N);
    gemm_sage_f16<<<mblocks, 256, SMEM>>>(feat16, agg16, w16, w16 + D * D,
                                          b1, h116, N, 0, nullptr, nullptr, nullptr);
    gather16_kernel<<<gblocks, 256>>>(h116, rowstart, csrsrc, agg16, N);
    gemm_sage_f16<<<mblocks, 256, SMEM>>>(h116, agg16, w16 + 2 * D * D, w16 + 3 * D * D,
                                          b2, nullptr, N, 1, Wc, bc, (float*)d_out);
}

// round 10
// speedup vs baseline: 2.9478x; 1.0441x over previous
#include <cuda_runtime.h>
#include <cuda_fp16.h>
#include <cstdint>

#define N_NODES 100000
#define N_EDGES 1600000
#define D 128
#define SCAN_B 256

// Scratch (allocation-free: __device__ globals)
__device__ int    g_cnt[N_NODES];
__device__ int    g_cursor[N_NODES];
__device__ int    g_rowstart[N_NODES + 1];
__device__ int    g_bsum[1024];
__device__ int    g_csrsrc[N_EDGES];
__device__ float  g_wfs[D * 2];
__device__ float  g_wfn[D * 2];
__device__ float  g_bf[2];
__device__ __align__(128) __half g_feat16[(size_t)N_NODES * D];
__device__ __align__(128) __half g_agg16[(size_t)N_NODES * D];
__device__ __align__(128) __half g_h116[(size_t)N_NODES * D];
__device__ __align__(128) __half g_w16[2][D * D];  // W1s^T, W1n^T (n-major)

// ---------------------------------------------------------------- helpers
__device__ __forceinline__ void mma_f16(float* d, const uint32_t* a, const uint32_t* b) {
    asm volatile(
        "mma.sync.aligned.m16n8k16.row.col.f32.f16.f16.f32 "
        "{%0,%1,%2,%3}, {%4,%5,%6,%7}, {%8,%9}, {%0,%1,%2,%3};"
        : "+f"(d[0]), "+f"(d[1]), "+f"(d[2]), "+f"(d[3])
        : "r"(a[0]), "r"(a[1]), "r"(a[2]), "r"(a[3]), "r"(b[0]), "r"(b[1]));
}
__device__ __forceinline__ void cp16(uint32_t dst, const void* src) {
    asm volatile("cp.async.cg.shared.global [%0], [%1], 16;" :: "r"(dst), "l"(src));
}
#define CP_COMMIT() asm volatile("cp.async.commit_group;" ::: "memory")
#define CP_WAIT(n)  asm volatile("cp.async.wait_group %0;" :: "n"(n) : "memory")

// ---------------------------------------------------------------- conversions
__global__ void conv16_kernel(const float* __restrict__ in, __half* __restrict__ out, int n4) {
    int i = blockIdx.x * blockDim.x + threadIdx.x;
    if (i >= n4) return;
    float4 v = __ldg((const float4*)in + i);
    __half2 h0 = __floats2half2_rn(v.x, v.y);
    __half2 h1 = __floats2half2_rn(v.z, v.w);
    uint2 o;
    o.x = *(uint32_t*)&h0;
    o.y = *(uint32_t*)&h1;
    ((uint2*)out)[i] = o;
}

// transpose+convert layer-1 weights [k][n] fp32 -> [n][k] fp16
__global__ void wconv_kernel(const float* __restrict__ W1s, const float* __restrict__ W1n) {
    int t = blockIdx.x * blockDim.x + threadIdx.x;   // 0 .. 2*16384-1
    int m = t >> 14;
    int i = t & 16383;
    int n = i >> 7, k = i & 127;
    const float* W = (m == 0) ? W1s : W1n;
    g_w16[m][i] = __float2half_rn(__ldg(W + k * D + n));
}

// fused layer-2 weights: Wfs = W2s@Wc, Wfn = W2n@Wc, bf = b2@Wc + bc
__global__ void wfuse_kernel(const float* __restrict__ W2s, const float* __restrict__ W2n,
                             const float* __restrict__ Wc, const float* __restrict__ b2,
                             const float* __restrict__ bc) {
    int t = threadIdx.x;           // 512 threads, 1 block
    int which = t >> 8;            // 0 -> Wfs, 1 -> Wfn
    int i = t & 255;
    int k = i >> 1, c = i & 1;
    const float* W = which ? W2n : W2s;
    float s = 0.f;
#pragma unroll 4
    for (int j = 0; j < D; j++) s += __ldg(W + k * D + j) * __ldg(Wc + j * 2 + c);
    if (which) g_wfn[i] = s; else g_wfs[i] = s;
    if (t < 2) {
        float sb = __ldg(bc + t);
        for (int j = 0; j < D; j++) sb += __ldg(b2 + j) * __ldg(Wc + j * 2 + t);
        g_bf[t] = sb;
    }
}

// ---------------------------------------------------------------- CSR build
__global__ void zero_cnt_kernel(int* __restrict__ cnt, int n) {
    int i = blockIdx.x * blockDim.x + threadIdx.x;
    if (i < n) cnt[i] = 0;
}

__global__ void hist_kernel(const int2* __restrict__ dst2, int* __restrict__ cnt, int E2) {
    int i = blockIdx.x * blockDim.x + threadIdx.x;
    if (i < E2) {
        int2 d = __ldg(dst2 + i);
        atomicAdd(&cnt[d.x], 1);
        atomicAdd(&cnt[d.y], 1);
    }
}

__global__ void scan_bsum_kernel(const int* __restrict__ cnt, int* __restrict__ bsum, int n) {
    __shared__ int sh[SCAN_B];
    int i = blockIdx.x * SCAN_B + threadIdx.x;
    sh[threadIdx.x] = (i < n) ? cnt[i] : 0;
    __syncthreads();
#pragma unroll
    for (int off = SCAN_B / 2; off; off >>= 1) {
        if (threadIdx.x < off) sh[threadIdx.x] += sh[threadIdx.x + off];
        __syncthreads();
    }
    if (threadIdx.x == 0) bsum[blockIdx.x] = sh[0];
}

__global__ void scan_top_kernel(int* __restrict__ bsum, int* __restrict__ rowstart,
                                int nb, int n) {
    __shared__ int sh[512];
    int t = threadIdx.x;
    int v = (t < nb) ? bsum[t] : 0;
    sh[t] = v;
    __syncthreads();
#pragma unroll
    for (int off = 1; off < 512; off <<= 1) {
        int u = (t >= off) ? sh[t - off] : 0;
        __syncthreads();
        sh[t] += u;
        __syncthreads();
    }
    if (t < nb) bsum[t] = sh[t] - v;
    if (t == 511) rowstart[n] = sh[511];
}

__global__ void scan_fin_kernel(const int* __restrict__ cnt, const int* __restrict__ bsum,
                                int* __restrict__ rowstart, int* __restrict__ cursor, int n) {
    __shared__ int sh[SCAN_B];
    int i = blockIdx.x * SCAN_B + threadIdx.x;
    int v = (i < n) ? cnt[i] : 0;
    sh[threadIdx.x] = v;
    __syncthreads();
#pragma unroll
    for (int off = 1; off < SCAN_B; off <<= 1) {
        int u = (threadIdx.x >= off) ? sh[threadIdx.x - off] : 0;
        __syncthreads();
        sh[threadIdx.x] += u;
        __syncthreads();
    }
    if (i < n) {
        int ex = sh[threadIdx.x] - v + bsum[blockIdx.x];
        rowstart[i] = ex;
        cursor[i] = ex;
    }
}

__global__ void fill2_kernel(const int2* __restrict__ src2, const int2* __restrict__ dst2,
                             int* __restrict__ cursor, int* __restrict__ csrsrc, int E2) {
    int i = blockIdx.x * blockDim.x + threadIdx.x;
    if (i < E2) {
        int2 s = __ldg(src2 + i);
        int2 d = __ldg(dst2 + i);
        int p0 = atomicAdd(&cursor[d.x], 1);
        csrsrc[p0] = s.x;
        int p1 = atomicAdd(&cursor[d.y], 1);
        csrsrc[p1] = s.y;
    }
}

// ---------------------------------------------------------------- layer-1 gather
__global__ void gather16_kernel(const __half* __restrict__ H, const int* __restrict__ rowstart,
                                const int* __restrict__ csrsrc, __half* __restrict__ agg, int N) {
    int w = (blockIdx.x * blockDim.x + threadIdx.x) >> 5;
    int lane = threadIdx.x & 31;
    if (w >= N) return;
    int beg = __ldg(rowstart + w);
    int end = __ldg(rowstart + w + 1);
    float2 a0 = make_float2(0.f, 0.f), a1 = make_float2(0.f, 0.f);
    float2 b0 = make_float2(0.f, 0.f), b1 = make_float2(0.f, 0.f);
    float2 c0 = make_float2(0.f, 0.f), c1 = make_float2(0.f, 0.f);
    float2 d0 = make_float2(0.f, 0.f), d1 = make_float2(0.f, 0.f);
    int i = beg;
    for (; i + 3 < end; i += 4) {
        int e0 = __ldg(csrsrc + i);
        int e1 = __ldg(csrsrc + i + 1);
        int e2 = __ldg(csrsrc + i + 2);
        int e3 = __ldg(csrsrc + i + 3);
        uint2 v0 = __ldg((const uint2*)(H + (size_t)e0 * D) + lane);
        uint2 v1 = __ldg((const uint2*)(H + (size_t)e1 * D) + lane);
        uint2 v2 = __ldg((const uint2*)(H + (size_t)e2 * D) + lane);
        uint2 v3 = __ldg((const uint2*)(H + (size_t)e3 * D) + lane);
        float2 p, q;
        p = __half22float2(*(__half2*)&v0.x); q = __half22float2(*(__half2*)&v0.y);
        a0.x += p.x; a0.y += p.y; a1.x += q.x; a1.y += q.y;
        p = __half22float2(*(__half2*)&v1.x); q = __half22float2(*(__half2*)&v1.y);
        b0.x += p.x; b0.y += p.y; b1.x += q.x; b1.y += q.y;
        p = __half22float2(*(__half2*)&v2.x); q = __half22float2(*(__half2*)&v2.y);
        c0.x += p.x; c0.y += p.y; c1.x += q.x; c1.y += q.y;
        p = __half22float2(*(__half2*)&v3.x); q = __half22float2(*(__half2*)&v3.y);
        d0.x += p.x; d0.y += p.y; d1.x += q.x; d1.y += q.y;
    }
    for (; i < end; i++) {
        int e0 = __ldg(csrsrc + i);
        uint2 v0 = __ldg((const uint2*)(H + (size_t)e0 * D) + lane);
        float2 p = __half22float2(*(__half2*)&v0.x);
        float2 q = __half22float2(*(__half2*)&v0.y);
        a0.x += p.x; a0.y += p.y; a1.x += q.x; a1.y += q.y;
    }
    float inv = 1.0f / (float)max(end - beg, 1);
    __half2 o0 = __floats2half2_rn((a0.x + b0.x + c0.x + d0.x) * inv,
                                   (a0.y + b0.y + c0.y + d0.y) * inv);
    __half2 o1 = __floats2half2_rn((a1.x + b1.x + c1.x + d1.x) * inv,
                                   (a1.y + b1.y + c1.y + d1.y) * inv);
    uint2 o;
    o.x = *(uint32_t*)&o0;
    o.y = *(uint32_t*)&o1;
    *((uint2*)(agg + (size_t)w * D) + lane) = o;
}

// ---------------------------------------------------------------- layer-2 fused
// out[m,0:2] = h1[m,:]@Wfs + mean_neighbors(h1)[m,:]@Wfn + bf  (gather + GEMV fused)
__global__ void layer2_kernel(const __half* __restrict__ H, const int* __restrict__ rowstart,
                              const int* __restrict__ csrsrc, const float* __restrict__ wfs,
                              const float* __restrict__ wfn, const float* __restrict__ bf,
                              float* __restrict__ out, int N) {
    int w = (blockIdx.x * blockDim.x + threadIdx.x) >> 5;
    int lane = threadIdx.x & 31;
    if (w >= N) return;
    // per-lane fused weights for k = lane*4 .. lane*4+3, classes 0/1 interleaved
    float4 ws0 = __ldg((const float4*)(wfs + lane * 8));
    float4 ws1 = __ldg((const float4*)(wfs + lane * 8 + 4));
    float4 wn0 = __ldg((const float4*)(wfn + lane * 8));
    float4 wn1 = __ldg((const float4*)(wfn + lane * 8 + 4));

    int beg = __ldg(rowstart + w);
    int end = __ldg(rowstart + w + 1);
    float2 a0 = make_float2(0.f, 0.f), a1 = make_float2(0.f, 0.f);
    float2 b0 = make_float2(0.f, 0.f), b1 = make_float2(0.f, 0.f);
    float2 c0 = make_float2(0.f, 0.f), c1 = make_float2(0.f, 0.f);
    float2 d0 = make_float2(0.f, 0.f), d1 = make_float2(0.f, 0.f);
    int i = beg;
    for (; i + 3 < end; i += 4) {
        int e0 = __ldg(csrsrc + i);
        int e1 = __ldg(csrsrc + i + 1);
        int e2 = __ldg(csrsrc + i + 2);
        int e3 = __ldg(csrsrc + i + 3);
        uint2 v0 = __ldg((const uint2*)(H + (size_t)e0 * D) + lane);
        uint2 v1 = __ldg((const uint2*)(H + (size_t)e1 * D) + lane);
        uint2 v2 = __ldg((const uint2*)(H + (size_t)e2 * D) + lane);
        uint2 v3 = __ldg((const uint2*)(H + (size_t)e3 * D) + lane);
        float2 p, q;
        p = __half22float2(*(__half2*)&v0.x); q = __half22float2(*(__half2*)&v0.y);
        a0.x += p.x; a0.y += p.y; a1.x += q.x; a1.y += q.y;
        p = __half22float2(*(__half2*)&v1.x); q = __half22float2(*(__half2*)&v1.y);
        b0.x += p.x; b0.y += p.y; b1.x += q.x; b1.y += q.y;
        p = __half22float2(*(__half2*)&v2.x); q = __half22float2(*(__half2*)&v2.y);
        c0.x += p.x; c0.y += p.y; c1.x += q.x; c1.y += q.y;
        p = __half22float2(*(__half2*)&v3.x); q = __half22float2(*(__half2*)&v3.y);
        d0.x += p.x; d0.y += p.y; d1.x += q.x; d1.y += q.y;
    }
    for (; i < end; i++) {
        int e0 = __ldg(csrsrc + i);
        uint2 v0 = __ldg((const uint2*)(H + (size_t)e0 * D) + lane);
        float2 p = __half22float2(*(__half2*)&v0.x);
        float2 q = __half22float2(*(__half2*)&v0.y);
        a0.x += p.x; a0.y += p.y; a1.x += q.x; a1.y += q.y;
    }
    float inv = 1.0f / (float)max(end - beg, 1);
    float g0 = (a0.x + b0.x + c0.x + d0.x) * inv;
    float g1 = (a0.y + b0.y + c0.y + d0.y) * inv;
    float g2 = (a1.x + b1.x + c1.x + d1.x) * inv;
    float g3 = (a1.y + b1.y + c1.y + d1.y) * inv;
    // self row
    uint2 sv = __ldg((const uint2*)(H + (size_t)w * D) + lane);
    float2 sp = __half22float2(*(__half2*)&sv.x);
    float2 sq = __half22float2(*(__half2*)&sv.y);
    // per-lane partial dots (wfs/wfn layout: [k][c] interleaved)
    float p0 = sp.x * ws0.x + sp.y * ws0.z + sq.x * ws1.x + sq.y * ws1.z
             + g0 * wn0.x + g1 * wn0.z + g2 * wn1.x + g3 * wn1.z;
    float p1 = sp.x * ws0.y + sp.y * ws0.w + sq.x * ws1.y + sq.y * ws1.w
             + g0 * wn0.y + g1 * wn0.w + g2 * wn1.y + g3 * wn1.w;
#pragma unroll
    for (int off = 16; off; off >>= 1) {
        p0 += __shfl_xor_sync(0xFFFFFFFFu, p0, off);
        p1 += __shfl_xor_sync(0xFFFFFFFFu, p1, off);
    }
    if (lane == 0) {
        out[(size_t)w * 2 + 0] = p0 + __ldg(bf);
        out[(size_t)w * 2 + 1] = p1 + __ldg(bf + 1);
    }
}

// ---------------------------------------------------------------- layer-1 GEMM
// h1 = relu( feat @ W1s + agg @ W1n + b1 ), fp16 out.
// Double-buffered cp.async, K chunks of 64 halves, swizzle v' = v ^ (r&7).
#define CHUNK_WORDS (128 * 32)
__global__ void __launch_bounds__(256, 2)
gemm_sage_f16(const __half* __restrict__ Aself, const __half* __restrict__ Aagg,
              const __half* __restrict__ Wself, const __half* __restrict__ Wneigh,
              const float* __restrict__ bias, __half* __restrict__ out, int M) {
    extern __shared__ __align__(16) uint32_t dyn[];
    uint32_t* Abuf[2] = {dyn, dyn + CHUNK_WORDS};
    uint32_t* Bbuf[2] = {dyn + 2 * CHUNK_WORDS, dyn + 3 * CHUNK_WORDS};

    int tid = threadIdx.x;
    int wid = tid >> 5;
    int lane = tid & 31;
    int wm = wid >> 1;
    int wn = wid & 1;
    int row0 = blockIdx.x * 128;

    const __half* Aarr[2] = {Aself, Aagg};
    const __half* Warr[2] = {Wself, Wneigh};

    float acc[2][8][4];
#pragma unroll
    for (int mt = 0; mt < 2; mt++)
#pragma unroll
        for (int nt = 0; nt < 8; nt++)
#pragma unroll
            for (int e = 0; e < 4; e++) acc[mt][nt][e] = 0.f;

    int s_r = tid >> 3;
    int s_v = tid & 7;
    uint32_t a_sm[2], b_sm[2];
#pragma unroll
    for (int b = 0; b < 2; b++) {
        a_sm[b] = (uint32_t)__cvta_generic_to_shared(Abuf[b]);
        b_sm[b] = (uint32_t)__cvta_generic_to_shared(Bbuf[b]);
    }

    int r0l = wm * 32 + (lane >> 2);
    int wlo = lane & 3;
    int n_row = wn * 64 + (lane >> 2);

    {
#pragma unroll
        for (int it = 0; it < 4; it++) {
            int r = s_r + it * 32;
            int gr = min(row0 + r, M - 1);
            uint32_t off = (uint32_t)((r * 8 + (s_v ^ (r & 7))) * 16);
            cp16(a_sm[0] + off, Aarr[0] + (size_t)gr * D + s_v * 8);
            cp16(b_sm[0] + off, Warr[0] + (size_t)r * D + s_v * 8);
        }
        CP_COMMIT();
    }

#pragma unroll 1
    for (int step = 0; step < 4; ++step) {
        if (step < 3) {
            int ns = step + 1;
            const __half* A = Aarr[ns >> 1];
            const __half* W = Warr[ns >> 1];
            int k0 = (ns & 1) * 64;
            int nb = ns & 1;
#pragma unroll
            for (int it = 0; it < 4; it++) {
                int r = s_r + it * 32;
                int gr = min(row0 + r, M - 1);
                uint32_t off = (uint32_t)((r * 8 + (s_v ^ (r & 7))) * 16);
                cp16(a_sm[nb] + off, A + (size_t)gr * D + k0 + s_v * 8);
                cp16(b_sm[nb] + off, W + (size_t)r * D + k0 + s_v * 8);
            }
            CP_COMMIT();
            CP_WAIT(1);
        } else {
            CP_WAIT(0);
        }
        __syncthreads();

        const uint32_t* As = Abuf[step & 1];
        const uint32_t* Bs = Bbuf[step & 1];
#pragma unroll
        for (int ks = 0; ks < 4; ks++) {
            uint32_t af[2][4];
#pragma unroll
            for (int mt = 0; mt < 2; mt++) {
                int r = r0l + mt * 16;
                int sw = r & 7;
                int v0 = (2 * ks) ^ sw, v1 = (2 * ks + 1) ^ sw;
                af[mt][0] = As[r * 32 + v0 * 4 + wlo];
                af[mt][1] = As[(r + 8) * 32 + v0 * 4 + wlo];
                af[mt][2] = As[r * 32 + v1 * 4 + wlo];
                af[mt][3] = As[(r + 8) * 32 + v1 * 4 + wlo];
            }
#pragma unroll
            for (int nt = 0; nt < 8; nt++) {
                int n = n_row + nt * 8;
                int swn = n & 7;
                uint32_t b2[2];
                b2[0] = Bs[n * 32 + ((2 * ks) ^ swn) * 4 + wlo];
                b2[1] = Bs[n * 32 + ((2 * ks + 1) ^ swn) * 4 + wlo];
#pragma unroll
                for (int mt = 0; mt < 2; mt++)
                    mma_f16(acc[mt][nt], af[mt], b2);
            }
        }
        __syncthreads();
    }

#pragma unroll
    for (int mt = 0; mt < 2; mt++) {
        int r = row0 + wm * 32 + mt * 16 + (lane >> 2);
#pragma unroll
        for (int nt = 0; nt < 8; nt++) {
            int c = wn * 64 + nt * 8 + (lane & 3) * 2;
            float b0 = __ldg(bias + c), b1 = __ldg(bias + c + 1);
            if (r < M) {
                __half2 o = __floats2half2_rn(fmaxf(acc[mt][nt][0] + b0, 0.f),
                                              fmaxf(acc[mt][nt][1] + b1, 0.f));
                *(__half2*)(out + (size_t)r * D + c) = o;
            }
            if (r + 8 < M) {
                __half2 o = __floats2half2_rn(fmaxf(acc[mt][nt][2] + b0, 0.f),
                                              fmaxf(acc[mt][nt][3] + b1, 0.f));
                *(__half2*)(out + (size_t)(r + 8) * D + c) = o;
            }
        }
    }
}

// ---------------------------------------------------------------- launch
extern "C" void kernel_launch(void* const* d_in, const int* in_sizes, int n_in,
                              void* d_out, int out_size) {
    const float* features = (const float*)d_in[0];
    const int*   src      = (const int*)d_in[1];
    const int*   dst      = (const int*)d_in[2];
    const float* W1s      = (const float*)d_in[3];
    const float* W1n      = (const float*)d_in[4];
    const float* b1       = (const float*)d_in[5];
    const float* W2s      = (const float*)d_in[6];
    const float* W2n      = (const float*)d_in[7];
    const float* b2       = (const float*)d_in[8];
    const float* Wc       = (const float*)d_in[9];
    const float* bc       = (const float*)d_in[10];

    int N = in_sizes[0] / D;
    int E = in_sizes[1];

    int *cnt, *cursor, *rowstart, *csrsrc, *bsum;
    float *wfs, *wfn, *bf;
    __half *feat16, *agg16, *h116, *w16;
    cudaGetSymbolAddress((void**)&cnt, g_cnt);
    cudaGetSymbolAddress((void**)&cursor, g_cursor);
    cudaGetSymbolAddress((void**)&rowstart, g_rowstart);
    cudaGetSymbolAddress((void**)&csrsrc, g_csrsrc);
    cudaGetSymbolAddress((void**)&bsum, g_bsum);
    cudaGetSymbolAddress((void**)&wfs, g_wfs);
    cudaGetSymbolAddress((void**)&wfn, g_wfn);
    cudaGetSymbolAddress((void**)&bf, g_bf);
    cudaGetSymbolAddress((void**)&feat16, g_feat16);
    cudaGetSymbolAddress((void**)&agg16, g_agg16);
    cudaGetSymbolAddress((void**)&h116, g_h116);
    cudaGetSymbolAddress((void**)&w16, g_w16);

    static cudaStream_t s1 = nullptr;
    static cudaEvent_t ev0 = nullptr, ev1 = nullptr;
    static int init_done = 0;
    if (!init_done) {
        cudaFuncSetAttribute(gemm_sage_f16,
                             cudaFuncAttributeMaxDynamicSharedMemorySize, 65536);
        if (cudaStreamCreateWithFlags(&s1, cudaStreamNonBlocking) != cudaSuccess) s1 = nullptr;
        if (s1) {
            cudaEventCreateWithFlags(&ev0, cudaEventDisableTiming);
            cudaEventCreateWithFlags(&ev1, cudaEventDisableTiming);
        }
        init_done = 1;
    }

    int mblocks = (N + 127) / 128;
    int gblocks = (N + 7) / 8;
    int n4 = N * (D / 4);
    int nb = (N + SCAN_B - 1) / SCAN_B;
    const int SMEM = 65536;

    // side stream: conversions + fused layer-2 weights
    cudaStream_t cs = s1 ? s1 : (cudaStream_t)0;
    if (s1) {
        cudaEventRecord(ev0, 0);
        cudaStreamWaitEvent(s1, ev0, 0);
    }
    conv16_kernel<<<(n4 + 255) / 256, 256, 0, cs>>>(features, feat16, n4);
    wconv_kernel<<<(2 * D * D + 255) / 256, 256, 0, cs>>>(W1s, W1n);
    wfuse_kernel<<<1, 512, 0, cs>>>(W2s, W2n, Wc, b2, bc);
    if (s1) cudaEventRecord(ev1, s1);

    // main stream: CSR build
    zero_cnt_kernel<<<(N + 255) / 256, 256>>>(cnt, N);
    hist_kernel<<<(E / 2 + 255) / 256, 256>>>((const int2*)dst, cnt, E / 2);
    scan_bsum_kernel<<<nb, SCAN_B>>>(cnt, bsum, N);
    scan_top_kernel<<<1, 512>>>(bsum, rowstart, nb, N);
    scan_fin_kernel<<<nb, SCAN_B>>>(cnt, bsum, rowstart, cursor, N);
    fill2_kernel<<<(E / 2 + 255) / 256, 256>>>((const int2*)src, (const int2*)dst,
                                               cursor, csrsrc, E / 2);

    if (s1) cudaStreamWaitEvent((cudaStream_t)0, ev1, 0);

    gather16_kernel<<<gblocks, 256>>>(feat16, rowstart, csrsrc, agg16, N);
    gemm_sage_f16<<<mblocks, 256, SMEM>>>(feat16, agg16, w16, w16 + D * D,
                                          b1, h116, N);
    layer2_kernel<<<gblocks, 256>>>(h116, rowstart, csrsrc, wfs, wfn, bf,
                                    (float*)d_out, N);
}

// round 12
// speedup vs baseline: 4.1490x; 1.4075x over previous
#include <cuda_runtime.h>
#include <cuda_fp16.h>
#include <cstdint>

#define N_NODES 100000
#define N_EDGES 1600000
#define D 128
#define SCAN_B 256

// Scratch (allocation-free: __device__ globals)
__device__ int    g_cnt[N_NODES];
__device__ int    g_cursor[N_NODES];
__device__ int    g_rowstart[N_NODES + 1];
__device__ int    g_bsum[1024];
__device__ int    g_csrsrc[N_EDGES];
__device__ float  g_wfs[D * 2];
__device__ float  g_wfn[D * 2];
__device__ float  g_bf[2];
__device__ __align__(16) float g_z[(size_t)N_NODES * 4];  // [self0,self1,neigh0,neigh1]
__device__ __align__(128) __half g_feat16[(size_t)N_NODES * D];
__device__ __align__(128) __half g_agg16[(size_t)N_NODES * D];
__device__ __align__(128) __half g_w16[2][D * D];  // W1s^T, W1n^T (n-major)

// ---------------------------------------------------------------- helpers
__device__ __forceinline__ void mma_f16(float* d, const uint32_t* a, const uint32_t* b) {
    asm volatile(
        "mma.sync.aligned.m16n8k16.row.col.f32.f16.f16.f32 "
        "{%0,%1,%2,%3}, {%4,%5,%6,%7}, {%8,%9}, {%0,%1,%2,%3};"
        : "+f"(d[0]), "+f"(d[1]), "+f"(d[2]), "+f"(d[3])
        : "r"(a[0]), "r"(a[1]), "r"(a[2]), "r"(a[3]), "r"(b[0]), "r"(b[1]));
}
__device__ __forceinline__ void cp16(uint32_t dst, const void* src) {
    asm volatile("cp.async.cg.shared.global [%0], [%1], 16;" :: "r"(dst), "l"(src));
}
#define CP_COMMIT() asm volatile("cp.async.commit_group;" ::: "memory")
#define CP_WAIT(n)  asm volatile("cp.async.wait_group %0;" :: "n"(n) : "memory")

// ---------------------------------------------------------------- conversions
__global__ void conv16_kernel(const float* __restrict__ in, __half* __restrict__ out, int n4) {
    int i = blockIdx.x * blockDim.x + threadIdx.x;
    if (i >= n4) return;
    float4 v = __ldg((const float4*)in + i);
    __half2 h0 = __floats2half2_rn(v.x, v.y);
    __half2 h1 = __floats2half2_rn(v.z, v.w);
    uint2 o;
    o.x = *(uint32_t*)&h0;
    o.y = *(uint32_t*)&h1;
    ((uint2*)out)[i] = o;
}

// transpose+convert layer-1 weights [k][n] fp32 -> [n][k] fp16
__global__ void wconv_kernel(const float* __restrict__ W1s, const float* __restrict__ W1n) {
    int t = blockIdx.x * blockDim.x + threadIdx.x;
    int m = t >> 14;
    int i = t & 16383;
    int n = i >> 7, k = i & 127;
    const float* W = (m == 0) ? W1s : W1n;
    g_w16[m][i] = __float2half_rn(__ldg(W + k * D + n));
}

// fused layer-2 weights: Wfs = W2s@Wc, Wfn = W2n@Wc, bf = b2@Wc + bc
__global__ void wfuse_kernel(const float* __restrict__ W2s, const float* __restrict__ W2n,
                             const float* __restrict__ Wc, const float* __restrict__ b2,
                             const float* __restrict__ bc) {
    int t = threadIdx.x;           // 512 threads, 1 block
    int which = t >> 8;
    int i = t & 255;
    int k = i >> 1, c = i & 1;
    const float* W = which ? W2n : W2s;
    float s = 0.f;
#pragma unroll 4
    for (int j = 0; j < D; j++) s += __ldg(W + k * D + j) * __ldg(Wc + j * 2 + c);
    if (which) g_wfn[i] = s; else g_wfs[i] = s;
    if (t < 2) {
        float sb = __ldg(bc + t);
        for (int j = 0; j < D; j++) sb += __ldg(b2 + j) * __ldg(Wc + j * 2 + t);
        g_bf[t] = sb;
    }
}

// ---------------------------------------------------------------- CSR build
__global__ void zero_cnt_kernel(int* __restrict__ cnt, int n) {
    int i = blockIdx.x * blockDim.x + threadIdx.x;
    if (i < n) cnt[i] = 0;
}

__global__ void hist_kernel(const int2* __restrict__ dst2, int* __restrict__ cnt, int E2) {
    int i = blockIdx.x * blockDim.x + threadIdx.x;
    if (i < E2) {
        int2 d = __ldg(dst2 + i);
        atomicAdd(&cnt[d.x], 1);
        atomicAdd(&cnt[d.y], 1);
    }
}

__global__ void scan_bsum_kernel(const int* __restrict__ cnt, int* __restrict__ bsum, int n) {
    __shared__ int sh[SCAN_B];
    int i = blockIdx.x * SCAN_B + threadIdx.x;
    sh[threadIdx.x] = (i < n) ? cnt[i] : 0;
    __syncthreads();
#pragma unroll
    for (int off = SCAN_B / 2; off; off >>= 1) {
        if (threadIdx.x < off) sh[threadIdx.x] += sh[threadIdx.x + off];
        __syncthreads();
    }
    if (threadIdx.x == 0) bsum[blockIdx.x] = sh[0];
}

__global__ void scan_top_kernel(int* __restrict__ bsum, int* __restrict__ rowstart,
                                int nb, int n) {
    __shared__ int sh[512];
    int t = threadIdx.x;
    int v = (t < nb) ? bsum[t] : 0;
    sh[t] = v;
    __syncthreads();
#pragma unroll
    for (int off = 1; off < 512; off <<= 1) {
        int u = (t >= off) ? sh[t - off] : 0;
        __syncthreads();
        sh[t] += u;
        __syncthreads();
    }
    if (t < nb) bsum[t] = sh[t] - v;
    if (t == 511) rowstart[n] = sh[511];
}

__global__ void scan_fin_kernel(const int* __restrict__ cnt, const int* __restrict__ bsum,
                                int* __restrict__ rowstart, int* __restrict__ cursor, int n) {
    __shared__ int sh[SCAN_B];
    int i = blockIdx.x * SCAN_B + threadIdx.x;
    int v = (i < n) ? cnt[i] : 0;
    sh[threadIdx.x] = v;
    __syncthreads();
#pragma unroll
    for (int off = 1; off < SCAN_B; off <<= 1) {
        int u = (threadIdx.x >= off) ? sh[threadIdx.x - off] : 0;
        __syncthreads();
        sh[threadIdx.x] += u;
        __syncthreads();
    }
    if (i < n) {
        int ex = sh[threadIdx.x] - v + bsum[blockIdx.x];
        rowstart[i] = ex;
        cursor[i] = ex;
    }
}

__global__ void fill2_kernel(const int2* __restrict__ src2, const int2* __restrict__ dst2,
                             int* __restrict__ cursor, int* __restrict__ csrsrc, int E2) {
    int i = blockIdx.x * blockDim.x + threadIdx.x;
    if (i < E2) {
        int2 s = __ldg(src2 + i);
        int2 d = __ldg(dst2 + i);
        int p0 = atomicAdd(&cursor[d.x], 1);
        csrsrc[p0] = s.x;
        int p1 = atomicAdd(&cursor[d.y], 1);
        csrsrc[p1] = s.y;
    }
}

// ---------------------------------------------------------------- layer-1 gather
__global__ void gather16_kernel(const __half* __restrict__ H, const int* __restrict__ rowstart,
                                const int* __restrict__ csrsrc, __half* __restrict__ agg, int N) {
    int w = (blockIdx.x * blockDim.x + threadIdx.x) >> 5;
    int lane = threadIdx.x & 31;
    if (w >= N) return;
    int beg = __ldg(rowstart + w);
    int end = __ldg(rowstart + w + 1);
    float2 a0 = make_float2(0.f, 0.f), a1 = make_float2(0.f, 0.f);
    float2 b0 = make_float2(0.f, 0.f), b1 = make_float2(0.f, 0.f);
    float2 c0 = make_float2(0.f, 0.f), c1 = make_float2(0.f, 0.f);
    float2 d0 = make_float2(0.f, 0.f), d1 = make_float2(0.f, 0.f);
    int i = beg;
    for (; i + 3 < end; i += 4) {
        int e0 = __ldg(csrsrc + i);
        int e1 = __ldg(csrsrc + i + 1);
        int e2 = __ldg(csrsrc + i + 2);
        int e3 = __ldg(csrsrc + i + 3);
        uint2 v0 = __ldg((const uint2*)(H + (size_t)e0 * D) + lane);
        uint2 v1 = __ldg((const uint2*)(H + (size_t)e1 * D) + lane);
        uint2 v2 = __ldg((const uint2*)(H + (size_t)e2 * D) + lane);
        uint2 v3 = __ldg((const uint2*)(H + (size_t)e3 * D) + lane);
        float2 p, q;
        p = __half22float2(*(__half2*)&v0.x); q = __half22float2(*(__half2*)&v0.y);
        a0.x += p.x; a0.y += p.y; a1.x += q.x; a1.y += q.y;
        p = __half22float2(*(__half2*)&v1.x); q = __half22float2(*(__half2*)&v1.y);
        b0.x += p.x; b0.y += p.y; b1.x += q.x; b1.y += q.y;
        p = __half22float2(*(__half2*)&v2.x); q = __half22float2(*(__half2*)&v2.y);
        c0.x += p.x; c0.y += p.y; c1.x += q.x; c1.y += q.y;
        p = __half22float2(*(__half2*)&v3.x); q = __half22float2(*(__half2*)&v3.y);
        d0.x += p.x; d0.y += p.y; d1.x += q.x; d1.y += q.y;
    }
    for (; i < end; i++) {
        int e0 = __ldg(csrsrc + i);
        uint2 v0 = __ldg((const uint2*)(H + (size_t)e0 * D) + lane);
        float2 p = __half22float2(*(__half2*)&v0.x);
        float2 q = __half22float2(*(__half2*)&v0.y);
        a0.x += p.x; a0.y += p.y; a1.x += q.x; a1.y += q.y;
    }
    float inv = 1.0f / (float)max(end - beg, 1);
    __half2 o0 = __floats2half2_rn((a0.x + b0.x + c0.x + d0.x) * inv,
                                   (a0.y + b0.y + c0.y + d0.y) * inv);
    __half2 o1 = __floats2half2_rn((a1.x + b1.x + c1.x + d1.x) * inv,
                                   (a1.y + b1.y + c1.y + d1.y) * inv);
    uint2 o;
    o.x = *(uint32_t*)&o0;
    o.y = *(uint32_t*)&o1;
    *((uint2*)(agg + (size_t)w * D) + lane) = o;
}

// ---------------------------------------------------------------- layer-1 GEMM + z epilogue
// h = relu( feat @ W1s + agg @ W1n + b1 )  [fp32, registers only]
// z[r] = ( h@Wfs , h@Wfn )  -> 4 floats per node. h is NOT materialized.
#define CHUNK_WORDS (128 * 32)
__global__ void __launch_bounds__(256, 2)
gemm_sage_f16(const __half* __restrict__ Aself, const __half* __restrict__ Aagg,
              const __half* __restrict__ Wself, const __half* __restrict__ Wneigh,
              const float* __restrict__ bias, int M,
              const float* __restrict__ Wfs, const float* __restrict__ Wfn,
              float* __restrict__ z) {
    extern __shared__ __align__(16) uint32_t dyn[];
    uint32_t* Abuf[2] = {dyn, dyn + CHUNK_WORDS};
    uint32_t* Bbuf[2] = {dyn + 2 * CHUNK_WORDS, dyn + 3 * CHUNK_WORDS};
    __shared__ float s_z[2][128][4];

    int tid = threadIdx.x;
    int wid = tid >> 5;
    int lane = tid & 31;
    int wm = wid >> 1;
    int wn = wid & 1;
    int row0 = blockIdx.x * 128;

    const __half* Aarr[2] = {Aself, Aagg};
    const __half* Warr[2] = {Wself, Wneigh};

    float acc[2][8][4];
#pragma unroll
    for (int mt = 0; mt < 2; mt++)
#pragma unroll
        for (int nt = 0; nt < 8; nt++)
#pragma unroll
            for (int e = 0; e < 4; e++) acc[mt][nt][e] = 0.f;

    int s_r = tid >> 3;
    int s_v = tid & 7;
    uint32_t a_sm[2], b_sm[2];
#pragma unroll
    for (int b = 0; b < 2; b++) {
        a_sm[b] = (uint32_t)__cvta_generic_to_shared(Abuf[b]);
        b_sm[b] = (uint32_t)__cvta_generic_to_shared(Bbuf[b]);
    }

    int r0l = wm * 32 + (lane >> 2);
    int wlo = lane & 3;
    int n_row = wn * 64 + (lane >> 2);

    {
#pragma unroll
        for (int it = 0; it < 4; it++) {
            int r = s_r + it * 32;
            int gr = min(row0 + r, M - 1);
            uint32_t off = (uint32_t)((r * 8 + (s_v ^ (r & 7))) * 16);
            cp16(a_sm[0] + off, Aarr[0] + (size_t)gr * D + s_v * 8);
            cp16(b_sm[0] + off, Warr[0] + (size_t)r * D + s_v * 8);
        }
        CP_COMMIT();
    }

#pragma unroll 1
    for (int step = 0; step < 4; ++step) {
        if (step < 3) {
            int ns = step + 1;
            const __half* A = Aarr[ns >> 1];
            const __half* W = Warr[ns >> 1];
            int k0 = (ns & 1) * 64;
            int nb = ns & 1;
#pragma unroll
            for (int it = 0; it < 4; it++) {
                int r = s_r + it * 32;
                int gr = min(row0 + r, M - 1);
                uint32_t off = (uint32_t)((r * 8 + (s_v ^ (r & 7))) * 16);
                cp16(a_sm[nb] + off, A + (size_t)gr * D + k0 + s_v * 8);
                cp16(b_sm[nb] + off, W + (size_t)r * D + k0 + s_v * 8);
            }
            CP_COMMIT();
            CP_WAIT(1);
        } else {
            CP_WAIT(0);
        }
        __syncthreads();

        const uint32_t* As = Abuf[step & 1];
        const uint32_t* Bs = Bbuf[step & 1];
#pragma unroll
        for (int ks = 0; ks < 4; ks++) {
            uint32_t af[2][4];
#pragma unroll
            for (int mt = 0; mt < 2; mt++) {
                int r = r0l + mt * 16;
                int sw = r & 7;
                int v0 = (2 * ks) ^ sw, v1 = (2 * ks + 1) ^ sw;
                af[mt][0] = As[r * 32 + v0 * 4 + wlo];
                af[mt][1] = As[(r + 8) * 32 + v0 * 4 + wlo];
                af[mt][2] = As[r * 32 + v1 * 4 + wlo];
                af[mt][3] = As[(r + 8) * 32 + v1 * 4 + wlo];
            }
#pragma unroll
            for (int nt = 0; nt < 8; nt++) {
                int n = n_row + nt * 8;
                int swn = n & 7;
                uint32_t b2[2];
                b2[0] = Bs[n * 32 + ((2 * ks) ^ swn) * 4 + wlo];
                b2[1] = Bs[n * 32 + ((2 * ks + 1) ^ swn) * 4 + wlo];
#pragma unroll
                for (int mt = 0; mt < 2; mt++)
                    mma_f16(acc[mt][nt], af[mt], b2);
            }
        }
        __syncthreads();
    }

    // ---- z epilogue: relu(h)+dots with Wfs/Wfn, reduce lanes then warps ----
#pragma unroll
    for (int mt = 0; mt < 2; mt++) {
        float zsl0 = 0.f, zsl1 = 0.f, znl0 = 0.f, znl1 = 0.f;  // row r (lo)
        float zsh0 = 0.f, zsh1 = 0.f, znh0 = 0.f, znh1 = 0.f;  // row r+8 (hi)
#pragma unroll
        for (int nt = 0; nt < 8; nt++) {
            int c = wn * 64 + nt * 8 + (lane & 3) * 2;
            float b0 = __ldg(bias + c), b1 = __ldg(bias + c + 1);
            float2 ws0 = __ldg((const float2*)(Wfs + (size_t)c * 2));
            float2 ws1 = __ldg((const float2*)(Wfs + (size_t)(c + 1) * 2));
            float2 wn0 = __ldg((const float2*)(Wfn + (size_t)c * 2));
            float2 wn1 = __ldg((const float2*)(Wfn + (size_t)(c + 1) * 2));
            float h0 = fmaxf(acc[mt][nt][0] + b0, 0.f);
            float h1 = fmaxf(acc[mt][nt][1] + b1, 0.f);
            float h2 = fmaxf(acc[mt][nt][2] + b0, 0.f);
            float h3 = fmaxf(acc[mt][nt][3] + b1, 0.f);
            zsl0 += h0 * ws0.x + h1 * ws1.x;  zsl1 += h0 * ws0.y + h1 * ws1.y;
            znl0 += h0 * wn0.x + h1 * wn1.x;  znl1 += h0 * wn0.y + h1 * wn1.y;
            zsh0 += h2 * ws0.x + h3 * ws1.x;  zsh1 += h2 * ws0.y + h3 * ws1.y;
            znh0 += h2 * wn0.x + h3 * wn1.x;  znh1 += h2 * wn0.y + h3 * wn1.y;
        }
#pragma unroll
        for (int off = 1; off <= 2; off <<= 1) {
            zsl0 += __shfl_xor_sync(0xFFFFFFFFu, zsl0, off);
            zsl1 += __shfl_xor_sync(0xFFFFFFFFu, zsl1, off);
            znl0 += __shfl_xor_sync(0xFFFFFFFFu, znl0, off);
            znl1 += __shfl_xor_sync(0xFFFFFFFFu, znl1, off);
            zsh0 += __shfl_xor_sync(0xFFFFFFFFu, zsh0, off);
            zsh1 += __shfl_xor_sync(0xFFFFFFFFu, zsh1, off);
            znh0 += __shfl_xor_sync(0xFFFFFFFFu, znh0, off);
            znh1 += __shfl_xor_sync(0xFFFFFFFFu, znh1, off);
        }
        if ((lane & 3) == 0) {
            int lr = wm * 32 + mt * 16 + (lane >> 2);
            s_z[wn][lr][0] = zsl0; s_z[wn][lr][1] = zsl1;
            s_z[wn][lr][2] = znl0; s_z[wn][lr][3] = znl1;
            s_z[wn][lr + 8][0] = zsh0; s_z[wn][lr + 8][1] = zsh1;
            s_z[wn][lr + 8][2] = znh0; s_z[wn][lr + 8][3] = znh1;
        }
    }
    __syncthreads();
    {
        int row = tid >> 1;
        int j = tid & 1;   // float2 half
        if (row0 + row < M) {
            float2 v;
            v.x = s_z[0][row][j * 2 + 0] + s_z[1][row][j * 2 + 0];
            v.y = s_z[0][row][j * 2 + 1] + s_z[1][row][j * 2 + 1];
            *(float2*)(z + (size_t)(row0 + row) * 4 + j * 2) = v;
        }
    }
}

// ---------------------------------------------------------------- final: 8-byte edge gather
__global__ void final_kernel(const float* __restrict__ z, const int* __restrict__ rowstart,
                             const int* __restrict__ csrsrc, const float* __restrict__ bf,
                             float* __restrict__ out, int N) {
    int m = blockIdx.x * blockDim.x + threadIdx.x;
    if (m >= N) return;
    int beg = __ldg(rowstart + m);
    int end = __ldg(rowstart + m + 1);
    float s0 = 0.f, s1 = 0.f, t0 = 0.f, t1 = 0.f;
    int i = beg;
    for (; i + 1 < end; i += 2) {
        int e0 = __ldg(csrsrc + i);
        int e1 = __ldg(csrsrc + i + 1);
        float2 z0 = __ldg((const float2*)(z + (size_t)e0 * 4) + 1);
        float2 z1 = __ldg((const float2*)(z + (size_t)e1 * 4) + 1);
        s0 += z0.x; s1 += z0.y;
        t0 += z1.x; t1 += z1.y;
    }
    if (i < end) {
        int e0 = __ldg(csrsrc + i);
        float2 z0 = __ldg((const float2*)(z + (size_t)e0 * 4) + 1);
        s0 += z0.x; s1 += z0.y;
    }
    float inv = 1.0f / (float)max(end - beg, 1);
    float2 zs = __ldg((const float2*)(z + (size_t)m * 4));
    out[(size_t)m * 2 + 0] = zs.x + (s0 + t0) * inv + __ldg(bf);
    out[(size_t)m * 2 + 1] = zs.y + (s1 + t1) * inv + __ldg(bf + 1);
}

// ---------------------------------------------------------------- launch
extern "C" void kernel_launch(void* const* d_in, const int* in_sizes, int n_in,
                              void* d_out, int out_size) {
    const float* features = (const float*)d_in[0];
    const int*   src      = (const int*)d_in[1];
    const int*   dst      = (const int*)d_in[2];
    const float* W1s      = (const float*)d_in[3];
    const float* W1n      = (const float*)d_in[4];
    const float* b1       = (const float*)d_in[5];
    const float* W2s      = (const float*)d_in[6];
    const float* W2n      = (const float*)d_in[7];
    const float* b2       = (const float*)d_in[8];
    const float* Wc       = (const float*)d_in[9];
    const float* bc       = (const float*)d_in[10];

    int N = in_sizes[0] / D;
    int E = in_sizes[1];

    int *cnt, *cursor, *rowstart, *csrsrc, *bsum;
    float *wfs, *wfn, *bf, *zbuf;
    __half *feat16, *agg16, *w16;
    cudaGetSymbolAddress((void**)&cnt, g_cnt);
    cudaGetSymbolAddress((void**)&cursor, g_cursor);
    cudaGetSymbolAddress((void**)&rowstart, g_rowstart);
    cudaGetSymbolAddress((void**)&csrsrc, g_csrsrc);
    cudaGetSymbolAddress((void**)&bsum, g_bsum);
    cudaGetSymbolAddress((void**)&wfs, g_wfs);
    cudaGetSymbolAddress((void**)&wfn, g_wfn);
    cudaGetSymbolAddress((void**)&bf, g_bf);
    cudaGetSymbolAddress((void**)&zbuf, g_z);
    cudaGetSymbolAddress((void**)&feat16, g_feat16);
    cudaGetSymbolAddress((void**)&agg16, g_agg16);
    cudaGetSymbolAddress((void**)&w16, g_w16);

    static cudaStream_t s1 = nullptr;
    static cudaEvent_t ev0 = nullptr, ev1 = nullptr;
    static int init_done = 0;
    if (!init_done) {
        cudaFuncSetAttribute(gemm_sage_f16,
                             cudaFuncAttributeMaxDynamicSharedMemorySize, 65536);
        if (cudaStreamCreateWithFlags(&s1, cudaStreamNonBlocking) != cudaSuccess) s1 = nullptr;
        if (s1) {
            cudaEventCreateWithFlags(&ev0, cudaEventDisableTiming);
            cudaEventCreateWithFlags(&ev1, cudaEventDisableTiming);
        }
        init_done = 1;
    }

    int mblocks = (N + 127) / 128;
    int gblocks = (N + 7) / 8;
    int n4 = N * (D / 4);
    int nb = (N + SCAN_B - 1) / SCAN_B;
    const int SMEM = 65536;

    // side stream: conversions + fused layer-2 weights
    cudaStream_t cs = s1 ? s1 : (cudaStream_t)0;
    if (s1) {
        cudaEventRecord(ev0, 0);
        cudaStreamWaitEvent(s1, ev0, 0);
    }
    conv16_kernel<<<(n4 + 255) / 256, 256, 0, cs>>>(features, feat16, n4);
    wconv_kernel<<<(2 * D * D + 255) / 256, 256, 0, cs>>>(W1s, W1n);
    wfuse_kernel<<<1, 512, 0, cs>>>(W2s, W2n, Wc, b2, bc);
    if (s1) cudaEventRecord(ev1, s1);

    // main stream: CSR build
    zero_cnt_kernel<<<(N + 255) / 256, 256>>>(cnt, N);
    hist_kernel<<<(E / 2 + 255) / 256, 256>>>((const int2*)dst, cnt, E / 2);
    scan_bsum_kernel<<<nb, SCAN_B>>>(cnt, bsum, N);
    scan_top_kernel<<<1, 512>>>(bsum, rowstart, nb, N);
    scan_fin_kernel<<<nb, SCAN_B>>>(cnt, bsum, rowstart, cursor, N);
    fill2_kernel<<<(E / 2 + 255) / 256, 256>>>((const int2*)src, (const int2*)dst,
                                               cursor, csrsrc, E / 2);

    if (s1) cudaStreamWaitEvent((cudaStream_t)0, ev1, 0);

    gather16_kernel<<<gblocks, 256>>>(feat16, rowstart, csrsrc, agg16, N);
    gemm_sage_f16<<<mblocks, 256, SMEM>>>(feat16, agg16, w16, w16 + D * D,
                                          b1, N, wfs, wfn, zbuf);
    final_kernel<<<(N + 255) / 256, 256>>>(zbuf, rowstart, csrsrc, bf,
                                           (float*)d_out, N);
}